// round 1
// baseline (speedup 1.0000x reference)
#include <cuda_runtime.h>

#define NN 100000
#define EE 1600000
#define F 64

// ---------------- device scratch (static: allocation-guard safe) ----------------
__device__ int   g_cnt_row[NN];
__device__ int   g_cnt_col[NN];
__device__ int   g_row_off[NN + 1];
__device__ int   g_col_off[NN + 1];
__device__ int   g_cur_row[NN];
__device__ int   g_cur_col[NN];
__device__ int   g_csr_col[EE];   // neighbors (col ids) grouped by row  -> Av
__device__ int   g_csc_row[EE];   // neighbors (row ids) grouped by col  -> Atv
__device__ float g_Avdin[NN], g_Avdout[NN], g_Atvdout[NN], g_Atvdin[NN];
__device__ float4 g_preA[NN];     // {isi, sAtA, sAAi, 0} pre-scales for round-1 Av
__device__ float4 g_preT[NN];     // {iso, sAAt, sAAo, 0} pre-scales for round-1 Atv
__device__ float g_post[6][NN];   // 0:iso 1:isi 2:sAAt 3:sAtA 4:sAAo 5:sAAi
__device__ float g_u[NN * F];     // Atv(sAAt*x)
__device__ float g_v[NN * F];     // Av (sAtA*x)
__device__ float g_w[NN * F];     // Av (sAAi*x)
__device__ float g_z[NN * F];     // Atv(sAAo*x)
__device__ float g_H[6][NN * F];  // A_x, At_x, AAt_x, AtA_x, AA_x, AtAt_x

// ---------------- CSR/CSC build ----------------
__global__ void k_zero(int n) {
    int i = blockIdx.x * blockDim.x + threadIdx.x;
    if (i < n) { g_cnt_row[i] = 0; g_cnt_col[i] = 0; }
}

__global__ void k_hist(const int* __restrict__ ei, int E) {
    int e = blockIdx.x * blockDim.x + threadIdx.x;
    if (e < E) {
        atomicAdd(&g_cnt_row[ei[e]], 1);
        atomicAdd(&g_cnt_col[ei[E + e]], 1);
    }
}

// single-block exclusive scan of n counts -> offsets (off[n] = total)
__global__ void k_scan(int dir, int n) {
    const int* cnt = dir ? g_cnt_col : g_cnt_row;
    int* off = dir ? g_col_off : g_row_off;
    __shared__ int sh[1024];
    int tid = threadIdx.x;
    int per = (n + 1023) >> 10;
    int start = tid * per;
    int end = min(start + per, n);
    int s = 0;
    for (int i = start; i < end; i++) s += cnt[i];
    sh[tid] = s;
    __syncthreads();
    for (int d = 1; d < 1024; d <<= 1) {
        int v = sh[tid];
        int add = (tid >= d) ? sh[tid - d] : 0;
        __syncthreads();
        sh[tid] = v + add;
        __syncthreads();
    }
    int total = sh[1023];
    int run = (tid > 0) ? sh[tid - 1] : 0;
    for (int i = start; i < end; i++) { off[i] = run; run += cnt[i]; }
    if (tid == 0) off[n] = total;
}

__global__ void k_cursor(int n) {
    int i = blockIdx.x * blockDim.x + threadIdx.x;
    if (i < n) { g_cur_row[i] = g_row_off[i]; g_cur_col[i] = g_col_off[i]; }
}

__global__ void k_scatter(const int* __restrict__ ei, int E) {
    int e = blockIdx.x * blockDim.x + threadIdx.x;
    if (e < E) {
        int r = ei[e], c = ei[E + e];
        int p = atomicAdd(&g_cur_row[r], 1);
        g_csr_col[p] = c;
        int q = atomicAdd(&g_cur_col[c], 1);
        g_csc_row[q] = r;
    }
}

// ---------------- scalar degree SpMVs (both per direction in one pass) -------
__global__ void k_degspmv(int dir, int n) {
    int i = blockIdx.x * blockDim.x + threadIdx.x;
    if (i >= n) return;
    const int* off = dir ? g_col_off : g_row_off;
    const int* nbr = dir ? g_csc_row : g_csr_col;
    const int* cA  = dir ? g_cnt_row : g_cnt_col;  // dir0: Av(d_in)  dir1: Atv(d_out)
    const int* cB  = dir ? g_cnt_col : g_cnt_row;  // dir0: Av(d_out) dir1: Atv(d_in)
    float* oA = dir ? g_Atvdout : g_Avdin;
    float* oB = dir ? g_Atvdin  : g_Avdout;
    int s = off[i], e = off[i + 1];
    int sa = 0, sb = 0;
    for (int j = s; j < e; j++) {
        int nb = __ldg(nbr + j);
        sa += __ldg(cA + nb);
        sb += __ldg(cB + nb);
    }
    oA[i] = (float)sa;
    oB[i] = (float)sb;
}

__device__ __forceinline__ float invsq(float d) {
    return d > 0.f ? 1.0f / sqrtf(d) : 0.0f;
}

__global__ void k_scales(int n) {
    int i = blockIdx.x * blockDim.x + threadIdx.x;
    if (i >= n) return;
    float iso  = invsq((float)g_cnt_row[i]);
    float isi  = invsq((float)g_cnt_col[i]);
    float sAAt = invsq(g_Avdin[i]);
    float sAtA = invsq(g_Atvdout[i]);
    float sAAo = invsq(g_Avdout[i]);
    float sAAi = invsq(g_Atvdin[i]);
    g_preA[i] = make_float4(isi, sAtA, sAAi, 0.f);
    g_preT[i] = make_float4(iso, sAAt, sAAo, 0.f);
    g_post[0][i] = iso;  g_post[1][i] = isi;
    g_post[2][i] = sAAt; g_post[3][i] = sAtA;
    g_post[4][i] = sAAo; g_post[5][i] = sAAi;
}

// ---------------- round-1 fused SpMM: 3 pre-scaled outputs from x ------------
// dir0 (Av):  out0=H0 (post iso), out1=v, out2=w    pre = {isi, sAtA, sAAi}
// dir1 (Atv): out0=H1 (post isi), out1=u, out2=z    pre = {iso, sAAt, sAAo}
__global__ void k_spmm3(int dir, const float* __restrict__ x, int n) {
    int gw = (blockIdx.x * blockDim.x + threadIdx.x) >> 5;
    int lane = threadIdx.x & 31;
    if (gw >= n) return;
    const int* off = dir ? g_col_off : g_row_off;
    const int* nbr = dir ? g_csc_row : g_csr_col;
    const float4* pre = dir ? g_preT : g_preA;
    const float* post0 = dir ? g_post[1] : g_post[0];
    float* out0 = dir ? g_H[1] : g_H[0];
    float* out1 = dir ? g_u : g_v;
    float* out2 = dir ? g_z : g_w;

    int s = off[gw], e = off[gw + 1];
    float a0x = 0.f, a0y = 0.f, a1x = 0.f, a1y = 0.f, a2x = 0.f, a2y = 0.f;
    for (int base = s; base < e; base += 32) {
        int idx = base + lane;
        int myn = 0;
        float4 mp = make_float4(0.f, 0.f, 0.f, 0.f);
        if (idx < e) {
            myn = __ldg(nbr + idx);
            mp = __ldg(pre + myn);
        }
        int cnt = min(32, e - base);
        for (int k = 0; k < cnt; k++) {
            int nd = __shfl_sync(0xffffffffu, myn, k);
            float p0 = __shfl_sync(0xffffffffu, mp.x, k);
            float p1 = __shfl_sync(0xffffffffu, mp.y, k);
            float p2 = __shfl_sync(0xffffffffu, mp.z, k);
            float2 vv = __ldg(((const float2*)(x + (size_t)nd * F)) + lane);
            a0x = fmaf(p0, vv.x, a0x); a0y = fmaf(p0, vv.y, a0y);
            a1x = fmaf(p1, vv.x, a1x); a1y = fmaf(p1, vv.y, a1y);
            a2x = fmaf(p2, vv.x, a2x); a2y = fmaf(p2, vv.y, a2y);
        }
    }
    float pp = post0[gw];
    size_t o = (size_t)gw * F + lane * 2;
    *(float2*)(out0 + o) = make_float2(pp * a0x, pp * a0y);
    *(float2*)(out1 + o) = make_float2(a1x, a1y);
    *(float2*)(out2 + o) = make_float2(a2x, a2y);
}

// ---------------- round-2 fused SpMM: 2 inputs, post-scaled outputs ----------
// dir0 (Av):  u -> H2 (post sAAt),  w -> H4 (post sAAo)
// dir1 (Atv): v -> H3 (post sAtA),  z -> H5 (post sAAi)
__global__ void k_spmm2(int dir, int n) {
    int gw = (blockIdx.x * blockDim.x + threadIdx.x) >> 5;
    int lane = threadIdx.x & 31;
    if (gw >= n) return;
    const int* off = dir ? g_col_off : g_row_off;
    const int* nbr = dir ? g_csc_row : g_csr_col;
    const float* in0 = dir ? g_v : g_u;
    const float* in1 = dir ? g_z : g_w;
    const float* post0 = dir ? g_post[3] : g_post[2];
    const float* post1 = dir ? g_post[5] : g_post[4];
    float* out0 = dir ? g_H[3] : g_H[2];
    float* out1 = dir ? g_H[5] : g_H[4];

    int s = off[gw], e = off[gw + 1];
    float a0x = 0.f, a0y = 0.f, a1x = 0.f, a1y = 0.f;
    for (int base = s; base < e; base += 32) {
        int idx = base + lane;
        int myn = 0;
        if (idx < e) myn = __ldg(nbr + idx);
        int cnt = min(32, e - base);
        for (int k = 0; k < cnt; k++) {
            int nd = __shfl_sync(0xffffffffu, myn, k);
            float2 v0 = __ldg(((const float2*)(in0 + (size_t)nd * F)) + lane);
            float2 v1 = __ldg(((const float2*)(in1 + (size_t)nd * F)) + lane);
            a0x += v0.x; a0y += v0.y;
            a1x += v1.x; a1y += v1.y;
        }
    }
    float p0 = post0[gw], p1 = post1[gw];
    size_t o = (size_t)gw * F + lane * 2;
    *(float2*)(out0 + o) = make_float2(p0 * a0x, p0 * a0y);
    *(float2*)(out1 + o) = make_float2(p1 * a1x, p1 * a1y);
}

// ---------------- fused 6-GEMM epilogue: out = 0.75*(sum H_i W_i + sum b_i) --
__global__ void k_gemm(const float* __restrict__ W0, const float* __restrict__ W1,
                       const float* __restrict__ W2, const float* __restrict__ W3,
                       const float* __restrict__ W4, const float* __restrict__ W5,
                       const float* __restrict__ B0, const float* __restrict__ B1,
                       const float* __restrict__ B2, const float* __restrict__ B3,
                       const float* __restrict__ B4, const float* __restrict__ B5,
                       float* __restrict__ out, int n) {
    __shared__ float sH[64 * 68];   // 64 rows, padded stride 68 (conflict-free)
    __shared__ float sW[64 * 64];
    const float* Ws[6] = {W0, W1, W2, W3, W4, W5};
    const float* Bs[6] = {B0, B1, B2, B3, B4, B5};

    int tid = threadIdx.x;
    int rowBase = blockIdx.x * 64;
    int ty = tid >> 4, tx = tid & 15;
    int r0 = ty * 4, c0 = tx * 4;

    float acc[4][4];
#pragma unroll
    for (int i = 0; i < 4; i++)
#pragma unroll
        for (int j = 0; j < 4; j++) acc[i][j] = 0.f;

#pragma unroll
    for (int m = 0; m < 6; m++) {
        const float* Hm = g_H[m];
        // cooperative load: 64x64 H tile (padded) + 64x64 W
        for (int idx = tid; idx < 1024; idx += 256) {
            int r = idx >> 4;
            int c = (idx & 15) * 4;
            float4 val = make_float4(0.f, 0.f, 0.f, 0.f);
            int gr = rowBase + r;
            if (gr < n) val = *(const float4*)(Hm + (size_t)gr * 64 + c);
            sH[r * 68 + c + 0] = val.x;
            sH[r * 68 + c + 1] = val.y;
            sH[r * 68 + c + 2] = val.z;
            sH[r * 68 + c + 3] = val.w;
            *(float4*)(sW + idx * 4) = __ldg(((const float4*)Ws[m]) + idx);
        }
        __syncthreads();
#pragma unroll 8
        for (int k = 0; k < 64; k++) {
            float4 bb = *(const float4*)(sW + k * 64 + c0);
            float a0 = sH[(r0 + 0) * 68 + k];
            float a1 = sH[(r0 + 1) * 68 + k];
            float a2 = sH[(r0 + 2) * 68 + k];
            float a3 = sH[(r0 + 3) * 68 + k];
            acc[0][0] = fmaf(a0, bb.x, acc[0][0]); acc[0][1] = fmaf(a0, bb.y, acc[0][1]);
            acc[0][2] = fmaf(a0, bb.z, acc[0][2]); acc[0][3] = fmaf(a0, bb.w, acc[0][3]);
            acc[1][0] = fmaf(a1, bb.x, acc[1][0]); acc[1][1] = fmaf(a1, bb.y, acc[1][1]);
            acc[1][2] = fmaf(a1, bb.z, acc[1][2]); acc[1][3] = fmaf(a1, bb.w, acc[1][3]);
            acc[2][0] = fmaf(a2, bb.x, acc[2][0]); acc[2][1] = fmaf(a2, bb.y, acc[2][1]);
            acc[2][2] = fmaf(a2, bb.z, acc[2][2]); acc[2][3] = fmaf(a2, bb.w, acc[2][3]);
            acc[3][0] = fmaf(a3, bb.x, acc[3][0]); acc[3][1] = fmaf(a3, bb.y, acc[3][1]);
            acc[3][2] = fmaf(a3, bb.z, acc[3][2]); acc[3][3] = fmaf(a3, bb.w, acc[3][3]);
        }
        __syncthreads();
    }

    float bias[4];
#pragma unroll
    for (int cc = 0; cc < 4; cc++) {
        float s = 0.f;
#pragma unroll
        for (int m = 0; m < 6; m++) s += __ldg(Bs[m] + c0 + cc);
        bias[cc] = s;
    }
#pragma unroll
    for (int rr = 0; rr < 4; rr++) {
        int gr = rowBase + r0 + rr;
        if (gr < n) {
            float4 o;
            o.x = 0.75f * (acc[rr][0] + bias[0]);
            o.y = 0.75f * (acc[rr][1] + bias[1]);
            o.z = 0.75f * (acc[rr][2] + bias[2]);
            o.w = 0.75f * (acc[rr][3] + bias[3]);
            *(float4*)(out + (size_t)gr * 64 + c0) = o;
        }
    }
}

// ---------------- launcher ----------------
extern "C" void kernel_launch(void* const* d_in, const int* in_sizes, int n_in,
                              void* d_out, int out_size) {
    const float* x = (const float*)d_in[0];
    const int* ei = (const int*)d_in[1];
    const float* W0 = (const float*)d_in[2],  *B0 = (const float*)d_in[3];
    const float* W1 = (const float*)d_in[4],  *B1 = (const float*)d_in[5];
    const float* W2 = (const float*)d_in[6],  *B2 = (const float*)d_in[7];
    const float* W3 = (const float*)d_in[8],  *B3 = (const float*)d_in[9];
    const float* W4 = (const float*)d_in[10], *B4 = (const float*)d_in[11];
    const float* W5 = (const float*)d_in[12], *B5 = (const float*)d_in[13];
    float* out = (float*)d_out;

    int n = in_sizes[0] / F;
    int E = in_sizes[1] / 2;
    if (n > NN) n = NN;
    if (E > EE) E = EE;

    int nb = (n + 255) / 256;
    int eb = (E + 255) / 256;

    k_zero<<<nb, 256>>>(n);
    k_hist<<<eb, 256>>>(ei, E);
    k_scan<<<1, 1024>>>(0, n);
    k_scan<<<1, 1024>>>(1, n);
    k_cursor<<<nb, 256>>>(n);
    k_scatter<<<eb, 256>>>(ei, E);
    k_degspmv<<<nb, 256>>>(0, n);
    k_degspmv<<<nb, 256>>>(1, n);
    k_scales<<<nb, 256>>>(n);

    int sb = (n + 7) / 8;   // warp-per-node, 8 warps/block
    k_spmm3<<<sb, 256>>>(0, x, n);
    k_spmm3<<<sb, 256>>>(1, x, n);
    k_spmm2<<<sb, 256>>>(0, n);
    k_spmm2<<<sb, 256>>>(1, n);

    int gb = (n + 63) / 64;
    k_gemm<<<gb, 256>>>(W0, W1, W2, W3, W4, W5,
                        B0, B1, B2, B3, B4, B5, out, n);
}

// round 2
// speedup vs baseline: 1.5426x; 1.5426x over previous
#include <cuda_runtime.h>

#define NN 100000
#define EE 1600000
#define F 64
#define SCAN_B 1024
#define MAXPB 128   // ceil(NN/1024) = 98 <= 128

// ---------------- device scratch (static: allocation-guard safe) ----------------
__device__ int   g_cnt_row[NN];
__device__ int   g_cnt_col[NN];
__device__ int   g_row_off[NN + 1];
__device__ int   g_col_off[NN + 1];
__device__ int   g_cur_row[NN];
__device__ int   g_cur_col[NN];
__device__ int   g_part[2][MAXPB];
__device__ int   g_partscan[2][MAXPB + 1];
__device__ int   g_csr_col[EE];   // neighbors (col ids) grouped by row  -> Av
__device__ int   g_csc_row[EE];   // neighbors (row ids) grouped by col  -> Atv
__device__ float g_Avdin[NN], g_Avdout[NN], g_Atvdout[NN], g_Atvdin[NN];
__device__ float4 g_preA[NN];     // {isi, sAtA, sAAi, 0} pre-scales for round-1 Av
__device__ float4 g_preT[NN];     // {iso, sAAt, sAAo, 0} pre-scales for round-1 Atv
__device__ float g_post[6][NN];   // 0:iso 1:isi 2:sAAt 3:sAtA 4:sAAo 5:sAAi
__device__ float g_u[NN * F];     // Atv(sAAt*x)
__device__ float g_v[NN * F];     // Av (sAtA*x)
__device__ float g_w[NN * F];     // Av (sAAi*x)
__device__ float g_z[NN * F];     // Atv(sAAo*x)
__device__ float g_H[6][NN * F];  // A_x, At_x, AAt_x, AtA_x, AA_x, AtAt_x

// ---------------- CSR/CSC build ----------------
__global__ void k_zero(int n) {
    int i = blockIdx.x * blockDim.x + threadIdx.x;
    if (i < n) { g_cnt_row[i] = 0; g_cnt_col[i] = 0; }
}

__global__ void k_hist(const int* __restrict__ ei, int E) {
    int e = blockIdx.x * blockDim.x + threadIdx.x;
    if (e < E) {
        atomicAdd(&g_cnt_row[ei[e]], 1);
        atomicAdd(&g_cnt_col[ei[E + e]], 1);
    }
}

// -------- multi-block exclusive scan: phase 1, per-block partial sums --------
__global__ void k_scan_part(int n) {
    int dir = blockIdx.y;
    const int* cnt = dir ? g_cnt_col : g_cnt_row;
    __shared__ int sh[256];
    int tid = threadIdx.x;
    int base = blockIdx.x * SCAN_B;
    int s = 0;
#pragma unroll
    for (int j = 0; j < 4; j++) {
        int i = base + tid + j * 256;
        if (i < n) s += cnt[i];
    }
    sh[tid] = s;
    __syncthreads();
    for (int d = 128; d > 0; d >>= 1) {
        if (tid < d) sh[tid] += sh[tid + d];
        __syncthreads();
    }
    if (tid == 0) g_part[dir][blockIdx.x] = sh[0];
}

// -------- phase 2: single block scans the <=128 partials for both dirs -------
__global__ void k_scan_mid(int pb) {
    __shared__ int sh[128];
    int tid = threadIdx.x;
    for (int dir = 0; dir < 2; dir++) {
        int v = (tid < pb) ? g_part[dir][tid] : 0;
        sh[tid] = v;
        __syncthreads();
        for (int d = 1; d < 128; d <<= 1) {
            int add = (tid >= d) ? sh[tid - d] : 0;
            __syncthreads();
            sh[tid] += add;
            __syncthreads();
        }
        if (tid < pb) g_partscan[dir][tid] = sh[tid] - v;   // exclusive
        if (tid == 0) g_partscan[dir][pb] = sh[127];        // total
        __syncthreads();
    }
}

// -------- phase 3: per-block scan + base; also init scatter cursors ----------
__global__ void k_scan_final(int n, int pb) {
    int dir = blockIdx.y;
    const int* cnt = dir ? g_cnt_col : g_cnt_row;
    int* off = dir ? g_col_off : g_row_off;
    int* cur = dir ? g_cur_col : g_cur_row;
    __shared__ int sh[SCAN_B];
    int tid = threadIdx.x;
    int i = blockIdx.x * SCAN_B + tid;
    int v = (i < n) ? cnt[i] : 0;
    sh[tid] = v;
    __syncthreads();
    for (int d = 1; d < SCAN_B; d <<= 1) {
        int add = (tid >= d) ? sh[tid - d] : 0;
        __syncthreads();
        sh[tid] += add;
        __syncthreads();
    }
    if (i < n) {
        int o = g_partscan[dir][blockIdx.x] + sh[tid] - v;  // exclusive
        off[i] = o;
        cur[i] = o;
    }
    if (blockIdx.x == 0 && tid == 0) off[n] = g_partscan[dir][pb];
}

__global__ void k_scatter(const int* __restrict__ ei, int E) {
    int e = blockIdx.x * blockDim.x + threadIdx.x;
    if (e < E) {
        int r = ei[e], c = ei[E + e];
        int p = atomicAdd(&g_cur_row[r], 1);
        g_csr_col[p] = c;
        int q = atomicAdd(&g_cur_col[c], 1);
        g_csc_row[q] = r;
    }
}

// ---------------- scalar degree SpMVs (both per direction in one pass) -------
__global__ void k_degspmv(int n) {
    int dir = blockIdx.y;
    int i = blockIdx.x * blockDim.x + threadIdx.x;
    if (i >= n) return;
    const int* off = dir ? g_col_off : g_row_off;
    const int* nbr = dir ? g_csc_row : g_csr_col;
    const int* cA  = dir ? g_cnt_row : g_cnt_col;  // dir0: Av(d_in)  dir1: Atv(d_out)
    const int* cB  = dir ? g_cnt_col : g_cnt_row;  // dir0: Av(d_out) dir1: Atv(d_in)
    float* oA = dir ? g_Atvdout : g_Avdin;
    float* oB = dir ? g_Atvdin  : g_Avdout;
    int s = off[i], e = off[i + 1];
    int sa = 0, sb = 0;
    for (int j = s; j < e; j++) {
        int nb = __ldg(nbr + j);
        sa += __ldg(cA + nb);
        sb += __ldg(cB + nb);
    }
    oA[i] = (float)sa;
    oB[i] = (float)sb;
}

__device__ __forceinline__ float invsq(float d) {
    return d > 0.f ? 1.0f / sqrtf(d) : 0.0f;
}

__global__ void k_scales(int n) {
    int i = blockIdx.x * blockDim.x + threadIdx.x;
    if (i >= n) return;
    float iso  = invsq((float)g_cnt_row[i]);
    float isi  = invsq((float)g_cnt_col[i]);
    float sAAt = invsq(g_Avdin[i]);
    float sAtA = invsq(g_Atvdout[i]);
    float sAAo = invsq(g_Avdout[i]);
    float sAAi = invsq(g_Atvdin[i]);
    g_preA[i] = make_float4(isi, sAtA, sAAi, 0.f);
    g_preT[i] = make_float4(iso, sAAt, sAAo, 0.f);
    g_post[0][i] = iso;  g_post[1][i] = isi;
    g_post[2][i] = sAAt; g_post[3][i] = sAtA;
    g_post[4][i] = sAAo; g_post[5][i] = sAAi;
}

// ---------------- round-1 fused SpMM: 3 pre-scaled outputs from x ------------
// dir0 (Av):  out0=H0 (post iso), out1=v, out2=w    pre = {isi, sAtA, sAAi}
// dir1 (Atv): out0=H1 (post isi), out1=u, out2=z    pre = {iso, sAAt, sAAo}
__global__ void k_spmm3(const float* __restrict__ x, int n) {
    int dir = blockIdx.y;
    int gw = (blockIdx.x * blockDim.x + threadIdx.x) >> 5;
    int lane = threadIdx.x & 31;
    if (gw >= n) return;
    const int* off = dir ? g_col_off : g_row_off;
    const int* nbr = dir ? g_csc_row : g_csr_col;
    const float4* pre = dir ? g_preT : g_preA;
    const float* post0 = dir ? g_post[1] : g_post[0];
    float* out0 = dir ? g_H[1] : g_H[0];
    float* out1 = dir ? g_u : g_v;
    float* out2 = dir ? g_z : g_w;

    int s = off[gw], e = off[gw + 1];
    float a0x = 0.f, a0y = 0.f, a1x = 0.f, a1y = 0.f, a2x = 0.f, a2y = 0.f;
    for (int base = s; base < e; base += 32) {
        int idx = base + lane;
        int myn = 0;
        float4 mp = make_float4(0.f, 0.f, 0.f, 0.f);
        if (idx < e) {
            myn = __ldg(nbr + idx);
            mp = __ldg(pre + myn);
        }
        int cnt = min(32, e - base);
        for (int k = 0; k < cnt; k++) {
            int nd = __shfl_sync(0xffffffffu, myn, k);
            float p0 = __shfl_sync(0xffffffffu, mp.x, k);
            float p1 = __shfl_sync(0xffffffffu, mp.y, k);
            float p2 = __shfl_sync(0xffffffffu, mp.z, k);
            float2 vv = __ldg(((const float2*)(x + (size_t)nd * F)) + lane);
            a0x = fmaf(p0, vv.x, a0x); a0y = fmaf(p0, vv.y, a0y);
            a1x = fmaf(p1, vv.x, a1x); a1y = fmaf(p1, vv.y, a1y);
            a2x = fmaf(p2, vv.x, a2x); a2y = fmaf(p2, vv.y, a2y);
        }
    }
    float pp = post0[gw];
    size_t o = (size_t)gw * F + lane * 2;
    *(float2*)(out0 + o) = make_float2(pp * a0x, pp * a0y);
    *(float2*)(out1 + o) = make_float2(a1x, a1y);
    *(float2*)(out2 + o) = make_float2(a2x, a2y);
}

// ---------------- round-2 fused SpMM: 2 inputs, post-scaled outputs ----------
// dir0 (Av):  u -> H2 (post sAAt),  w -> H4 (post sAAo)
// dir1 (Atv): v -> H3 (post sAtA),  z -> H5 (post sAAi)
__global__ void k_spmm2(int n) {
    int dir = blockIdx.y;
    int gw = (blockIdx.x * blockDim.x + threadIdx.x) >> 5;
    int lane = threadIdx.x & 31;
    if (gw >= n) return;
    const int* off = dir ? g_col_off : g_row_off;
    const int* nbr = dir ? g_csc_row : g_csr_col;
    const float* in0 = dir ? g_v : g_u;
    const float* in1 = dir ? g_z : g_w;
    const float* post0 = dir ? g_post[3] : g_post[2];
    const float* post1 = dir ? g_post[5] : g_post[4];
    float* out0 = dir ? g_H[3] : g_H[2];
    float* out1 = dir ? g_H[5] : g_H[4];

    int s = off[gw], e = off[gw + 1];
    float a0x = 0.f, a0y = 0.f, a1x = 0.f, a1y = 0.f;
    for (int base = s; base < e; base += 32) {
        int idx = base + lane;
        int myn = 0;
        if (idx < e) myn = __ldg(nbr + idx);
        int cnt = min(32, e - base);
        for (int k = 0; k < cnt; k++) {
            int nd = __shfl_sync(0xffffffffu, myn, k);
            float2 v0 = __ldg(((const float2*)(in0 + (size_t)nd * F)) + lane);
            float2 v1 = __ldg(((const float2*)(in1 + (size_t)nd * F)) + lane);
            a0x += v0.x; a0y += v0.y;
            a1x += v1.x; a1y += v1.y;
        }
    }
    float p0 = post0[gw], p1 = post1[gw];
    size_t o = (size_t)gw * F + lane * 2;
    *(float2*)(out0 + o) = make_float2(p0 * a0x, p0 * a0y);
    *(float2*)(out1 + o) = make_float2(p1 * a1x, p1 * a1y);
}

// ---------------- fused 6-GEMM epilogue: out = 0.75*(sum H_i W_i + sum b_i) --
__global__ void k_gemm(const float* __restrict__ W0, const float* __restrict__ W1,
                       const float* __restrict__ W2, const float* __restrict__ W3,
                       const float* __restrict__ W4, const float* __restrict__ W5,
                       const float* __restrict__ B0, const float* __restrict__ B1,
                       const float* __restrict__ B2, const float* __restrict__ B3,
                       const float* __restrict__ B4, const float* __restrict__ B5,
                       float* __restrict__ out, int n) {
    __shared__ float sH[64 * 68];   // 64 rows, padded stride 68 (conflict-free)
    __shared__ float sW[64 * 64];
    const float* Ws[6] = {W0, W1, W2, W3, W4, W5};
    const float* Bs[6] = {B0, B1, B2, B3, B4, B5};

    int tid = threadIdx.x;
    int rowBase = blockIdx.x * 64;
    int ty = tid >> 4, tx = tid & 15;
    int r0 = ty * 4, c0 = tx * 4;

    float acc[4][4];
#pragma unroll
    for (int i = 0; i < 4; i++)
#pragma unroll
        for (int j = 0; j < 4; j++) acc[i][j] = 0.f;

#pragma unroll
    for (int m = 0; m < 6; m++) {
        const float* Hm = g_H[m];
        for (int idx = tid; idx < 1024; idx += 256) {
            int r = idx >> 4;
            int c = (idx & 15) * 4;
            float4 val = make_float4(0.f, 0.f, 0.f, 0.f);
            int gr = rowBase + r;
            if (gr < n) val = *(const float4*)(Hm + (size_t)gr * 64 + c);
            sH[r * 68 + c + 0] = val.x;
            sH[r * 68 + c + 1] = val.y;
            sH[r * 68 + c + 2] = val.z;
            sH[r * 68 + c + 3] = val.w;
            *(float4*)(sW + idx * 4) = __ldg(((const float4*)Ws[m]) + idx);
        }
        __syncthreads();
#pragma unroll 8
        for (int k = 0; k < 64; k++) {
            float4 bb = *(const float4*)(sW + k * 64 + c0);
            float a0 = sH[(r0 + 0) * 68 + k];
            float a1 = sH[(r0 + 1) * 68 + k];
            float a2 = sH[(r0 + 2) * 68 + k];
            float a3 = sH[(r0 + 3) * 68 + k];
            acc[0][0] = fmaf(a0, bb.x, acc[0][0]); acc[0][1] = fmaf(a0, bb.y, acc[0][1]);
            acc[0][2] = fmaf(a0, bb.z, acc[0][2]); acc[0][3] = fmaf(a0, bb.w, acc[0][3]);
            acc[1][0] = fmaf(a1, bb.x, acc[1][0]); acc[1][1] = fmaf(a1, bb.y, acc[1][1]);
            acc[1][2] = fmaf(a1, bb.z, acc[1][2]); acc[1][3] = fmaf(a1, bb.w, acc[1][3]);
            acc[2][0] = fmaf(a2, bb.x, acc[2][0]); acc[2][1] = fmaf(a2, bb.y, acc[2][1]);
            acc[2][2] = fmaf(a2, bb.z, acc[2][2]); acc[2][3] = fmaf(a2, bb.w, acc[2][3]);
            acc[3][0] = fmaf(a3, bb.x, acc[3][0]); acc[3][1] = fmaf(a3, bb.y, acc[3][1]);
            acc[3][2] = fmaf(a3, bb.z, acc[3][2]); acc[3][3] = fmaf(a3, bb.w, acc[3][3]);
        }
        __syncthreads();
    }

    float bias[4];
#pragma unroll
    for (int cc = 0; cc < 4; cc++) {
        float s = 0.f;
#pragma unroll
        for (int m = 0; m < 6; m++) s += __ldg(Bs[m] + c0 + cc);
        bias[cc] = s;
    }
#pragma unroll
    for (int rr = 0; rr < 4; rr++) {
        int gr = rowBase + r0 + rr;
        if (gr < n) {
            float4 o;
            o.x = 0.75f * (acc[rr][0] + bias[0]);
            o.y = 0.75f * (acc[rr][1] + bias[1]);
            o.z = 0.75f * (acc[rr][2] + bias[2]);
            o.w = 0.75f * (acc[rr][3] + bias[3]);
            *(float4*)(out + (size_t)gr * 64 + c0) = o;
        }
    }
}

// ---------------- launcher ----------------
extern "C" void kernel_launch(void* const* d_in, const int* in_sizes, int n_in,
                              void* d_out, int out_size) {
    const float* x = (const float*)d_in[0];
    const int* ei = (const int*)d_in[1];
    const float* W0 = (const float*)d_in[2],  *B0 = (const float*)d_in[3];
    const float* W1 = (const float*)d_in[4],  *B1 = (const float*)d_in[5];
    const float* W2 = (const float*)d_in[6],  *B2 = (const float*)d_in[7];
    const float* W3 = (const float*)d_in[8],  *B3 = (const float*)d_in[9];
    const float* W4 = (const float*)d_in[10], *B4 = (const float*)d_in[11];
    const float* W5 = (const float*)d_in[12], *B5 = (const float*)d_in[13];
    float* out = (float*)d_out;

    int n = in_sizes[0] / F;
    int E = in_sizes[1] / 2;
    if (n > NN) n = NN;
    if (E > EE) E = EE;

    int nb = (n + 255) / 256;
    int eb = (E + 255) / 256;
    int pb = (n + SCAN_B - 1) / SCAN_B;

    k_zero<<<nb, 256>>>(n);
    k_hist<<<eb, 256>>>(ei, E);
    k_scan_part<<<dim3(pb, 2), 256>>>(n);
    k_scan_mid<<<1, 128>>>(pb);
    k_scan_final<<<dim3(pb, 2), SCAN_B>>>(n, pb);
    k_scatter<<<eb, 256>>>(ei, E);
    k_degspmv<<<dim3(nb, 2), 256>>>(n);
    k_scales<<<nb, 256>>>(n);

    int sb = (n + 7) / 8;   // warp-per-node, 8 warps/block
    k_spmm3<<<dim3(sb, 2), 256>>>(x, n);
    k_spmm2<<<dim3(sb, 2), 256>>>(n);

    int gb = (n + 63) / 64;
    k_gemm<<<gb, 256>>>(W0, W1, W2, W3, W4, W5,
                        B0, B1, B2, B3, B4, B5, out, n);
}

// round 3
// speedup vs baseline: 1.5534x; 1.0070x over previous
#include <cuda_runtime.h>
#include <cstdint>

#define NN 100000
#define EE 1600000
#define F 64
#define SCAN_B 1024
#define MAXPB 128   // ceil(NN/1024) = 98 <= 128

// ---------------- device scratch (static: allocation-guard safe) ----------------
__device__ int   g_cnt_row[NN];
__device__ int   g_cnt_col[NN];
__device__ int   g_row_off[NN + 1];
__device__ int   g_col_off[NN + 1];
__device__ int   g_cur_row[NN];
__device__ int   g_cur_col[NN];
__device__ int   g_part[2][MAXPB];
__device__ int   g_partscan[2][MAXPB + 1];
__device__ int   g_csr_col[EE];   // neighbors (col ids) grouped by row  -> Av
__device__ int   g_csc_row[EE];   // neighbors (row ids) grouped by col  -> Atv
__device__ float g_Avdin[NN], g_Avdout[NN], g_Atvdout[NN], g_Atvdin[NN];
__device__ float4 g_preA[NN];     // {isi, sAtA, sAAi, 0} pre-scales for round-1 Av
__device__ float4 g_preT[NN];     // {iso, sAAt, sAAo, 0} pre-scales for round-1 Atv
__device__ float g_post[6][NN];   // 0:iso 1:isi 2:sAAt 3:sAtA 4:sAAo 5:sAAi
__device__ float g_u[NN * F];     // Atv(sAAt*x)
__device__ float g_v[NN * F];     // Av (sAtA*x)
__device__ float g_w[NN * F];     // Av (sAAi*x)
__device__ float g_z[NN * F];     // Atv(sAAo*x)
__device__ float g_H[6][NN * F];  // A_x, At_x, AAt_x, AtA_x, AA_x, AtAt_x

// ---------------- CSR/CSC build ----------------
__global__ void k_zero(int n) {
    int i = blockIdx.x * blockDim.x + threadIdx.x;
    if (i < n) { g_cnt_row[i] = 0; g_cnt_col[i] = 0; }
}

__global__ void k_hist(const int* __restrict__ ei, int E) {
    int e = blockIdx.x * blockDim.x + threadIdx.x;
    if (e < E) {
        atomicAdd(&g_cnt_row[ei[e]], 1);
        atomicAdd(&g_cnt_col[ei[E + e]], 1);
    }
}

// -------- multi-block exclusive scan: phase 1, per-block partial sums --------
__global__ void k_scan_part(int n) {
    int dir = blockIdx.y;
    const int* cnt = dir ? g_cnt_col : g_cnt_row;
    __shared__ int sh[256];
    int tid = threadIdx.x;
    int base = blockIdx.x * SCAN_B;
    int s = 0;
#pragma unroll
    for (int j = 0; j < 4; j++) {
        int i = base + tid + j * 256;
        if (i < n) s += cnt[i];
    }
    sh[tid] = s;
    __syncthreads();
    for (int d = 128; d > 0; d >>= 1) {
        if (tid < d) sh[tid] += sh[tid + d];
        __syncthreads();
    }
    if (tid == 0) g_part[dir][blockIdx.x] = sh[0];
}

// -------- phase 2: single block scans the <=128 partials for both dirs -------
__global__ void k_scan_mid(int pb) {
    __shared__ int sh[128];
    int tid = threadIdx.x;
    for (int dir = 0; dir < 2; dir++) {
        int v = (tid < pb) ? g_part[dir][tid] : 0;
        sh[tid] = v;
        __syncthreads();
        for (int d = 1; d < 128; d <<= 1) {
            int add = (tid >= d) ? sh[tid - d] : 0;
            __syncthreads();
            sh[tid] += add;
            __syncthreads();
        }
        if (tid < pb) g_partscan[dir][tid] = sh[tid] - v;   // exclusive
        if (tid == 0) g_partscan[dir][pb] = sh[127];        // total
        __syncthreads();
    }
}

// -------- phase 3: per-block scan + base; also init scatter cursors ----------
__global__ void k_scan_final(int n, int pb) {
    int dir = blockIdx.y;
    const int* cnt = dir ? g_cnt_col : g_cnt_row;
    int* off = dir ? g_col_off : g_row_off;
    int* cur = dir ? g_cur_col : g_cur_row;
    __shared__ int sh[SCAN_B];
    int tid = threadIdx.x;
    int i = blockIdx.x * SCAN_B + tid;
    int v = (i < n) ? cnt[i] : 0;
    sh[tid] = v;
    __syncthreads();
    for (int d = 1; d < SCAN_B; d <<= 1) {
        int add = (tid >= d) ? sh[tid - d] : 0;
        __syncthreads();
        sh[tid] += add;
        __syncthreads();
    }
    if (i < n) {
        int o = g_partscan[dir][blockIdx.x] + sh[tid] - v;  // exclusive
        off[i] = o;
        cur[i] = o;
    }
    if (blockIdx.x == 0 && tid == 0) off[n] = g_partscan[dir][pb];
}

__global__ void k_scatter(const int* __restrict__ ei, int E) {
    int e = blockIdx.x * blockDim.x + threadIdx.x;
    if (e < E) {
        int r = ei[e], c = ei[E + e];
        int p = atomicAdd(&g_cur_row[r], 1);
        g_csr_col[p] = c;
        int q = atomicAdd(&g_cur_col[c], 1);
        g_csc_row[q] = r;
    }
}

// ---------------- scalar degree SpMVs (both per direction in one pass) -------
__global__ void k_degspmv(int n) {
    int dir = blockIdx.y;
    int i = blockIdx.x * blockDim.x + threadIdx.x;
    if (i >= n) return;
    const int* off = dir ? g_col_off : g_row_off;
    const int* nbr = dir ? g_csc_row : g_csr_col;
    const int* cA  = dir ? g_cnt_row : g_cnt_col;  // dir0: Av(d_in)  dir1: Atv(d_out)
    const int* cB  = dir ? g_cnt_col : g_cnt_row;  // dir0: Av(d_out) dir1: Atv(d_in)
    float* oA = dir ? g_Atvdout : g_Avdin;
    float* oB = dir ? g_Atvdin  : g_Avdout;
    int s = off[i], e = off[i + 1];
    int sa = 0, sb = 0;
    for (int j = s; j < e; j++) {
        int nb = __ldg(nbr + j);
        sa += __ldg(cA + nb);
        sb += __ldg(cB + nb);
    }
    oA[i] = (float)sa;
    oB[i] = (float)sb;
}

__device__ __forceinline__ float invsq(float d) {
    return d > 0.f ? 1.0f / sqrtf(d) : 0.0f;
}

__global__ void k_scales(int n) {
    int i = blockIdx.x * blockDim.x + threadIdx.x;
    if (i >= n) return;
    float iso  = invsq((float)g_cnt_row[i]);
    float isi  = invsq((float)g_cnt_col[i]);
    float sAAt = invsq(g_Avdin[i]);
    float sAtA = invsq(g_Atvdout[i]);
    float sAAo = invsq(g_Avdout[i]);
    float sAAi = invsq(g_Atvdin[i]);
    g_preA[i] = make_float4(isi, sAtA, sAAi, 0.f);
    g_preT[i] = make_float4(iso, sAAt, sAAo, 0.f);
    g_post[0][i] = iso;  g_post[1][i] = isi;
    g_post[2][i] = sAAt; g_post[3][i] = sAtA;
    g_post[4][i] = sAAo; g_post[5][i] = sAAi;
}

// ---------------- round-1 fused SpMM: 3 pre-scaled outputs from x ------------
__global__ void k_spmm3(const float* __restrict__ x, int n) {
    int dir = blockIdx.y;
    int gw = (blockIdx.x * blockDim.x + threadIdx.x) >> 5;
    int lane = threadIdx.x & 31;
    if (gw >= n) return;
    const int* off = dir ? g_col_off : g_row_off;
    const int* nbr = dir ? g_csc_row : g_csr_col;
    const float4* pre = dir ? g_preT : g_preA;
    const float* post0 = dir ? g_post[1] : g_post[0];
    float* out0 = dir ? g_H[1] : g_H[0];
    float* out1 = dir ? g_u : g_v;
    float* out2 = dir ? g_z : g_w;

    int s = off[gw], e = off[gw + 1];
    float a0x = 0.f, a0y = 0.f, a1x = 0.f, a1y = 0.f, a2x = 0.f, a2y = 0.f;
    for (int base = s; base < e; base += 32) {
        int idx = base + lane;
        int myn = 0;
        float4 mp = make_float4(0.f, 0.f, 0.f, 0.f);
        if (idx < e) {
            myn = __ldg(nbr + idx);
            mp = __ldg(pre + myn);
        }
        int cnt = min(32, e - base);
        for (int k = 0; k < cnt; k++) {
            int nd = __shfl_sync(0xffffffffu, myn, k);
            float p0 = __shfl_sync(0xffffffffu, mp.x, k);
            float p1 = __shfl_sync(0xffffffffu, mp.y, k);
            float p2 = __shfl_sync(0xffffffffu, mp.z, k);
            float2 vv = __ldg(((const float2*)(x + (size_t)nd * F)) + lane);
            a0x = fmaf(p0, vv.x, a0x); a0y = fmaf(p0, vv.y, a0y);
            a1x = fmaf(p1, vv.x, a1x); a1y = fmaf(p1, vv.y, a1y);
            a2x = fmaf(p2, vv.x, a2x); a2y = fmaf(p2, vv.y, a2y);
        }
    }
    float pp = post0[gw];
    size_t o = (size_t)gw * F + lane * 2;
    *(float2*)(out0 + o) = make_float2(pp * a0x, pp * a0y);
    *(float2*)(out1 + o) = make_float2(a1x, a1y);
    *(float2*)(out2 + o) = make_float2(a2x, a2y);
}

// ---------------- round-2 fused SpMM: 2 inputs, post-scaled outputs ----------
__global__ void k_spmm2(int n) {
    int dir = blockIdx.y;
    int gw = (blockIdx.x * blockDim.x + threadIdx.x) >> 5;
    int lane = threadIdx.x & 31;
    if (gw >= n) return;
    const int* off = dir ? g_col_off : g_row_off;
    const int* nbr = dir ? g_csc_row : g_csr_col;
    const float* in0 = dir ? g_v : g_u;
    const float* in1 = dir ? g_z : g_w;
    const float* post0 = dir ? g_post[3] : g_post[2];
    const float* post1 = dir ? g_post[5] : g_post[4];
    float* out0 = dir ? g_H[3] : g_H[2];
    float* out1 = dir ? g_H[5] : g_H[4];

    int s = off[gw], e = off[gw + 1];
    float a0x = 0.f, a0y = 0.f, a1x = 0.f, a1y = 0.f;
    for (int base = s; base < e; base += 32) {
        int idx = base + lane;
        int myn = 0;
        if (idx < e) myn = __ldg(nbr + idx);
        int cnt = min(32, e - base);
        for (int k = 0; k < cnt; k++) {
            int nd = __shfl_sync(0xffffffffu, myn, k);
            float2 v0 = __ldg(((const float2*)(in0 + (size_t)nd * F)) + lane);
            float2 v1 = __ldg(((const float2*)(in1 + (size_t)nd * F)) + lane);
            a0x += v0.x; a0y += v0.y;
            a1x += v1.x; a1y += v1.y;
        }
    }
    float p0 = post0[gw], p1 = post1[gw];
    size_t o = (size_t)gw * F + lane * 2;
    *(float2*)(out0 + o) = make_float2(p0 * a0x, p0 * a0y);
    *(float2*)(out1 + o) = make_float2(p1 * a1x, p1 * a1y);
}

// ---------------- tf32 tensor-core GEMM epilogue (3xTF32 compensated) --------
// out = 0.75 * (sum_m H_m @ W_m + sum_m b_m)
// Block: 64 rows x 64 cols. 8 warps: 2 row-groups (32) x 4 col-groups (16).
// mma.sync.m16n8k8.row.col.f32.tf32.tf32.f32
__device__ __forceinline__ uint32_t f2tf(float x) {
    uint32_t r;
    asm("cvt.rna.tf32.f32 %0, %1;" : "=r"(r) : "f"(x));
    return r;
}

__device__ __forceinline__ void mma_tf32(float* c, uint32_t a0, uint32_t a1,
                                         uint32_t a2, uint32_t a3,
                                         uint32_t b0, uint32_t b1) {
    asm volatile(
        "mma.sync.aligned.m16n8k8.row.col.f32.tf32.tf32.f32 "
        "{%0,%1,%2,%3}, {%4,%5,%6,%7}, {%8,%9}, {%0,%1,%2,%3};"
        : "+f"(c[0]), "+f"(c[1]), "+f"(c[2]), "+f"(c[3])
        : "r"(a0), "r"(a1), "r"(a2), "r"(a3), "r"(b0), "r"(b1));
}

#define LDP 68   // padded smem leading dim: bank = (4g+t) -> conflict-free

__global__ __launch_bounds__(256, 2) void k_gemm(
        const float* __restrict__ W0, const float* __restrict__ W1,
        const float* __restrict__ W2, const float* __restrict__ W3,
        const float* __restrict__ W4, const float* __restrict__ W5,
        const float* __restrict__ B0, const float* __restrict__ B1,
        const float* __restrict__ B2, const float* __restrict__ B3,
        const float* __restrict__ B4, const float* __restrict__ B5,
        float* __restrict__ out, int n) {
    __shared__ float sH[64 * LDP];    // H tile, row-major [row][k]
    __shared__ float sW[64 * LDP];    // W tile, TRANSPOSED: [n][k]
    __shared__ float sBias[64];
    const float* Ws[6] = {W0, W1, W2, W3, W4, W5};
    const float* Bs[6] = {B0, B1, B2, B3, B4, B5};

    int tid = threadIdx.x;
    int rowBase = blockIdx.x * 64;
    int w = tid >> 5;
    int lane = tid & 31;
    int g = lane >> 2;          // groupID 0..7
    int t = lane & 3;           // thread in group 0..3
    int wr = (w & 1) * 32;      // warp row offset in tile
    int wc = (w >> 1) * 16;     // warp col offset in tile

    if (tid < 64) {
        float s = 0.f;
#pragma unroll
        for (int m = 0; m < 6; m++) s += __ldg(Bs[m] + tid);
        sBias[tid] = s;
    }

    float acc[2][2][4];   // [m-tile][n-tile][frag]
#pragma unroll
    for (int i = 0; i < 2; i++)
#pragma unroll
        for (int j = 0; j < 2; j++)
#pragma unroll
            for (int q = 0; q < 4; q++) acc[i][j][q] = 0.f;

#pragma unroll
    for (int m = 0; m < 6; m++) {
        const float* Hm = g_H[m];
        const float* Wm = Ws[m];
        // load H tile (64x64): 256 thr x 4 float4
#pragma unroll
        for (int it = 0; it < 4; it++) {
            int idx = tid + it * 256;        // float4 index over 1024
            int r = idx >> 4;
            int c4 = (idx & 15) << 2;
            int gr = rowBase + r;
            float4 val = make_float4(0.f, 0.f, 0.f, 0.f);
            if (gr < n) val = *(const float4*)(Hm + (size_t)gr * 64 + c4);
            *(float4*)(&sH[r * LDP + c4]) = val;
        }
        // load W transposed: sW[nn][k] = W[k][nn]
#pragma unroll
        for (int it = 0; it < 4; it++) {
            int idx = tid + it * 256;
            int k = idx >> 4;
            int c4 = (idx & 15) << 2;
            float4 val = __ldg((const float4*)(Wm + k * 64 + c4));
            sW[(c4 + 0) * LDP + k] = val.x;
            sW[(c4 + 1) * LDP + k] = val.y;
            sW[(c4 + 2) * LDP + k] = val.z;
            sW[(c4 + 3) * LDP + k] = val.w;
        }
        __syncthreads();

#pragma unroll
        for (int kk = 0; kk < 64; kk += 8) {
            // A fragments: 2 m-tiles (rows wr+mt*16 .. +15)
            uint32_t ahi[2][4], alo[2][4];
#pragma unroll
            for (int mt = 0; mt < 2; mt++) {
                int rbase = wr + mt * 16;
                float f0 = sH[(rbase + g) * LDP + kk + t];
                float f1 = sH[(rbase + g + 8) * LDP + kk + t];
                float f2 = sH[(rbase + g) * LDP + kk + t + 4];
                float f3 = sH[(rbase + g + 8) * LDP + kk + t + 4];
                ahi[mt][0] = f2tf(f0); alo[mt][0] = f2tf(f0 - __uint_as_float(ahi[mt][0]));
                ahi[mt][1] = f2tf(f1); alo[mt][1] = f2tf(f1 - __uint_as_float(ahi[mt][1]));
                ahi[mt][2] = f2tf(f2); alo[mt][2] = f2tf(f2 - __uint_as_float(ahi[mt][2]));
                ahi[mt][3] = f2tf(f3); alo[mt][3] = f2tf(f3 - __uint_as_float(ahi[mt][3]));
            }
            // B fragments: 2 n-tiles (cols wc+nt .. +7); sW is [n][k]
            uint32_t bhi[2][2], blo[2][2];
#pragma unroll
            for (int nt = 0; nt < 2; nt++) {
                int nbase = wc + nt * 8;
                float f0 = sW[(nbase + g) * LDP + kk + t];       // b0: k=t,  n=g
                float f1 = sW[(nbase + g) * LDP + kk + t + 4];   // b1: k=t+4
                bhi[nt][0] = f2tf(f0); blo[nt][0] = f2tf(f0 - __uint_as_float(bhi[nt][0]));
                bhi[nt][1] = f2tf(f1); blo[nt][1] = f2tf(f1 - __uint_as_float(bhi[nt][1]));
            }
#pragma unroll
            for (int mt = 0; mt < 2; mt++)
#pragma unroll
                for (int nt = 0; nt < 2; nt++) {
                    mma_tf32(acc[mt][nt], alo[mt][0], alo[mt][1], alo[mt][2], alo[mt][3],
                             bhi[nt][0], bhi[nt][1]);
                    mma_tf32(acc[mt][nt], ahi[mt][0], ahi[mt][1], ahi[mt][2], ahi[mt][3],
                             blo[nt][0], blo[nt][1]);
                    mma_tf32(acc[mt][nt], ahi[mt][0], ahi[mt][1], ahi[mt][2], ahi[mt][3],
                             bhi[nt][0], bhi[nt][1]);
                }
        }
        __syncthreads();
    }

    // epilogue: out = 0.75*(acc + biasSum)
#pragma unroll
    for (int mt = 0; mt < 2; mt++) {
#pragma unroll
        for (int nt = 0; nt < 2; nt++) {
            int col = wc + nt * 8 + 2 * t;
            float bx = sBias[col], by = sBias[col + 1];
            int r1 = rowBase + wr + mt * 16 + g;
            int r2 = r1 + 8;
            if (r1 < n) {
                float2 o;
                o.x = 0.75f * (acc[mt][nt][0] + bx);
                o.y = 0.75f * (acc[mt][nt][1] + by);
                *(float2*)(out + (size_t)r1 * 64 + col) = o;
            }
            if (r2 < n) {
                float2 o;
                o.x = 0.75f * (acc[mt][nt][2] + bx);
                o.y = 0.75f * (acc[mt][nt][3] + by);
                *(float2*)(out + (size_t)r2 * 64 + col) = o;
            }
        }
    }
}

// ---------------- launcher ----------------
extern "C" void kernel_launch(void* const* d_in, const int* in_sizes, int n_in,
                              void* d_out, int out_size) {
    const float* x = (const float*)d_in[0];
    const int* ei = (const int*)d_in[1];
    const float* W0 = (const float*)d_in[2],  *B0 = (const float*)d_in[3];
    const float* W1 = (const float*)d_in[4],  *B1 = (const float*)d_in[5];
    const float* W2 = (const float*)d_in[6],  *B2 = (const float*)d_in[7];
    const float* W3 = (const float*)d_in[8],  *B3 = (const float*)d_in[9];
    const float* W4 = (const float*)d_in[10], *B4 = (const float*)d_in[11];
    const float* W5 = (const float*)d_in[12], *B5 = (const float*)d_in[13];
    float* out = (float*)d_out;

    int n = in_sizes[0] / F;
    int E = in_sizes[1] / 2;
    if (n > NN) n = NN;
    if (E > EE) E = EE;

    int nb = (n + 255) / 256;
    int eb = (E + 255) / 256;
    int pb = (n + SCAN_B - 1) / SCAN_B;

    k_zero<<<nb, 256>>>(n);
    k_hist<<<eb, 256>>>(ei, E);
    k_scan_part<<<dim3(pb, 2), 256>>>(n);
    k_scan_mid<<<1, 128>>>(pb);
    k_scan_final<<<dim3(pb, 2), SCAN_B>>>(n, pb);
    k_scatter<<<eb, 256>>>(ei, E);
    k_degspmv<<<dim3(nb, 2), 256>>>(n);
    k_scales<<<nb, 256>>>(n);

    int sb = (n + 7) / 8;   // warp-per-node, 8 warps/block
    k_spmm3<<<dim3(sb, 2), 256>>>(x, n);
    k_spmm2<<<dim3(sb, 2), 256>>>(n);

    int gb = (n + 63) / 64;
    k_gemm<<<gb, 256>>>(W0, W1, W2, W3, W4, W5,
                        B0, B1, B2, B3, B4, B5, out, n);
}

// round 4
// speedup vs baseline: 1.6916x; 1.0889x over previous
#include <cuda_runtime.h>
#include <cuda_fp16.h>
#include <cstdint>

#define NN 100000
#define EE 1600000
#define F 64
#define SCAN_B 1024
#define MAXPB 128   // ceil(NN/1024) = 98 <= 128

// ---------------- device scratch (static: allocation-guard safe) ----------------
__device__ int   g_cnt_row[NN];
__device__ int   g_cnt_col[NN];
__device__ int   g_row_off[NN + 1];
__device__ int   g_col_off[NN + 1];
__device__ int   g_cur_row[NN];
__device__ int   g_cur_col[NN];
__device__ int   g_part[2][MAXPB];
__device__ int   g_partscan[2][MAXPB + 1];
__device__ int   g_csr_col[EE];   // neighbors (col ids) grouped by row  -> Av
__device__ int   g_csc_row[EE];   // neighbors (row ids) grouped by col  -> Atv
__device__ float g_Avdin[NN], g_Avdout[NN], g_Atvdout[NN], g_Atvdin[NN];
__device__ float4 g_preA[NN];     // {isi, sAtA, sAAi, 0} pre-scales for round-1 Av
__device__ float4 g_preT[NN];     // {iso, sAAt, sAAo, 0} pre-scales for round-1 Atv
__device__ float g_post[6][NN];   // 0:iso 1:isi 2:sAAt 3:sAtA 4:sAAo 5:sAAi
// packed fp16 intermediates: per node 128 halves (256B)
// g_uw[node][0:64]  = u = Atv(sAAt*x),  g_uw[node][64:128] = w = Av(sAAi*x)
// g_vz[node][0:64]  = v = Av(sAtA*x),   g_vz[node][64:128] = z = Atv(sAAo*x)
__device__ __half g_uw[(size_t)NN * 128];
__device__ __half g_vz[(size_t)NN * 128];
__device__ __half g_Hh[6][(size_t)NN * F];  // A_x, At_x, AAt_x, AtA_x, AA_x, AtAt_x

// ---------------- CSR/CSC build ----------------
__global__ void k_zero(int n) {
    int i = blockIdx.x * blockDim.x + threadIdx.x;
    if (i < n) { g_cnt_row[i] = 0; g_cnt_col[i] = 0; }
}

__global__ void k_hist(const int* __restrict__ ei, int E) {
    int e = blockIdx.x * blockDim.x + threadIdx.x;
    if (e < E) {
        atomicAdd(&g_cnt_row[ei[e]], 1);
        atomicAdd(&g_cnt_col[ei[E + e]], 1);
    }
}

// -------- multi-block exclusive scan: phase 1, per-block partial sums --------
__global__ void k_scan_part(int n) {
    int dir = blockIdx.y;
    const int* cnt = dir ? g_cnt_col : g_cnt_row;
    __shared__ int sh[256];
    int tid = threadIdx.x;
    int base = blockIdx.x * SCAN_B;
    int s = 0;
#pragma unroll
    for (int j = 0; j < 4; j++) {
        int i = base + tid + j * 256;
        if (i < n) s += cnt[i];
    }
    sh[tid] = s;
    __syncthreads();
    for (int d = 128; d > 0; d >>= 1) {
        if (tid < d) sh[tid] += sh[tid + d];
        __syncthreads();
    }
    if (tid == 0) g_part[dir][blockIdx.x] = sh[0];
}

// -------- phase 2: single block scans the <=128 partials for both dirs -------
__global__ void k_scan_mid(int pb) {
    __shared__ int sh[128];
    int tid = threadIdx.x;
    for (int dir = 0; dir < 2; dir++) {
        int v = (tid < pb) ? g_part[dir][tid] : 0;
        sh[tid] = v;
        __syncthreads();
        for (int d = 1; d < 128; d <<= 1) {
            int add = (tid >= d) ? sh[tid - d] : 0;
            __syncthreads();
            sh[tid] += add;
            __syncthreads();
        }
        if (tid < pb) g_partscan[dir][tid] = sh[tid] - v;   // exclusive
        if (tid == 0) g_partscan[dir][pb] = sh[127];        // total
        __syncthreads();
    }
}

// -------- phase 3: per-block scan + base; also init scatter cursors ----------
__global__ void k_scan_final(int n, int pb) {
    int dir = blockIdx.y;
    const int* cnt = dir ? g_cnt_col : g_cnt_row;
    int* off = dir ? g_col_off : g_row_off;
    int* cur = dir ? g_cur_col : g_cur_row;
    __shared__ int sh[SCAN_B];
    int tid = threadIdx.x;
    int i = blockIdx.x * SCAN_B + tid;
    int v = (i < n) ? cnt[i] : 0;
    sh[tid] = v;
    __syncthreads();
    for (int d = 1; d < SCAN_B; d <<= 1) {
        int add = (tid >= d) ? sh[tid - d] : 0;
        __syncthreads();
        sh[tid] += add;
        __syncthreads();
    }
    if (i < n) {
        int o = g_partscan[dir][blockIdx.x] + sh[tid] - v;  // exclusive
        off[i] = o;
        cur[i] = o;
    }
    if (blockIdx.x == 0 && tid == 0) off[n] = g_partscan[dir][pb];
}

__global__ void k_scatter(const int* __restrict__ ei, int E) {
    int e = blockIdx.x * blockDim.x + threadIdx.x;
    if (e < E) {
        int r = ei[e], c = ei[E + e];
        int p = atomicAdd(&g_cur_row[r], 1);
        g_csr_col[p] = c;
        int q = atomicAdd(&g_cur_col[c], 1);
        g_csc_row[q] = r;
    }
}

// ---------------- scalar degree SpMVs (both per direction in one pass) -------
__global__ void k_degspmv(int n) {
    int dir = blockIdx.y;
    int i = blockIdx.x * blockDim.x + threadIdx.x;
    if (i >= n) return;
    const int* off = dir ? g_col_off : g_row_off;
    const int* nbr = dir ? g_csc_row : g_csr_col;
    const int* cA  = dir ? g_cnt_row : g_cnt_col;  // dir0: Av(d_in)  dir1: Atv(d_out)
    const int* cB  = dir ? g_cnt_col : g_cnt_row;  // dir0: Av(d_out) dir1: Atv(d_in)
    float* oA = dir ? g_Atvdout : g_Avdin;
    float* oB = dir ? g_Atvdin  : g_Avdout;
    int s = off[i], e = off[i + 1];
    int sa = 0, sb = 0;
    for (int j = s; j < e; j++) {
        int nb = __ldg(nbr + j);
        sa += __ldg(cA + nb);
        sb += __ldg(cB + nb);
    }
    oA[i] = (float)sa;
    oB[i] = (float)sb;
}

__device__ __forceinline__ float invsq(float d) {
    return d > 0.f ? 1.0f / sqrtf(d) : 0.0f;
}

__global__ void k_scales(int n) {
    int i = blockIdx.x * blockDim.x + threadIdx.x;
    if (i >= n) return;
    float iso  = invsq((float)g_cnt_row[i]);
    float isi  = invsq((float)g_cnt_col[i]);
    float sAAt = invsq(g_Avdin[i]);
    float sAtA = invsq(g_Atvdout[i]);
    float sAAo = invsq(g_Avdout[i]);
    float sAAi = invsq(g_Atvdin[i]);
    g_preA[i] = make_float4(isi, sAtA, sAAi, 0.f);
    g_preT[i] = make_float4(iso, sAAt, sAAo, 0.f);
    g_post[0][i] = iso;  g_post[1][i] = isi;
    g_post[2][i] = sAAt; g_post[3][i] = sAtA;
    g_post[4][i] = sAAo; g_post[5][i] = sAAi;
}

// ---------------- round-1 fused SpMM: 3 pre-scaled outputs from x ------------
// dir0 (Av):  out0=H0 (post iso) [half], out1=v -> g_vz[0:64], out2=w -> g_uw[64:128]
// dir1 (Atv): out0=H1 (post isi) [half], out1=u -> g_uw[0:64], out2=z -> g_vz[64:128]
__global__ void k_spmm3(const float* __restrict__ x, int n) {
    int dir = blockIdx.y;
    int gw = (blockIdx.x * blockDim.x + threadIdx.x) >> 5;
    int lane = threadIdx.x & 31;
    if (gw >= n) return;
    const int* off = dir ? g_col_off : g_row_off;
    const int* nbr = dir ? g_csc_row : g_csr_col;
    const float4* pre = dir ? g_preT : g_preA;
    const float* post0 = dir ? g_post[1] : g_post[0];
    __half* out0 = g_Hh[dir];
    __half* out1 = dir ? g_uw : g_vz;          // u / v -> first 64 halves
    __half* out2 = dir ? g_vz : g_uw;          // z / w -> last 64 halves

    int s = off[gw], e = off[gw + 1];
    float a0x = 0.f, a0y = 0.f, a1x = 0.f, a1y = 0.f, a2x = 0.f, a2y = 0.f;
    for (int base = s; base < e; base += 32) {
        int idx = base + lane;
        int myn = 0;
        float4 mp = make_float4(0.f, 0.f, 0.f, 0.f);
        if (idx < e) {
            myn = __ldg(nbr + idx);
            mp = __ldg(pre + myn);
        }
        int cnt = min(32, e - base);
        for (int k = 0; k < cnt; k++) {
            int nd = __shfl_sync(0xffffffffu, myn, k);
            float p0 = __shfl_sync(0xffffffffu, mp.x, k);
            float p1 = __shfl_sync(0xffffffffu, mp.y, k);
            float p2 = __shfl_sync(0xffffffffu, mp.z, k);
            float2 vv = __ldg(((const float2*)(x + (size_t)nd * F)) + lane);
            a0x = fmaf(p0, vv.x, a0x); a0y = fmaf(p0, vv.y, a0y);
            a1x = fmaf(p1, vv.x, a1x); a1y = fmaf(p1, vv.y, a1y);
            a2x = fmaf(p2, vv.x, a2x); a2y = fmaf(p2, vv.y, a2y);
        }
    }
    float pp = post0[gw];
    *(__half2*)(out0 + (size_t)gw * F + lane * 2) = __floats2half2_rn(pp * a0x, pp * a0y);
    *(__half2*)(out1 + (size_t)gw * 128 + lane * 2) = __floats2half2_rn(a1x, a1y);
    *(__half2*)(out2 + (size_t)gw * 128 + 64 + lane * 2) = __floats2half2_rn(a2x, a2y);
}

// ---------------- round-2 fused SpMM: one 256B gather per edge ----------------
// dir0 (Av over g_uw):  lanes 0-15 sum u -> H2 (post sAAt), lanes 16-31 sum w -> H4 (post sAAo)
// dir1 (Atv over g_vz): lanes 0-15 sum v -> H3 (post sAtA), lanes 16-31 sum z -> H5 (post sAAi)
__global__ void k_spmm2(int n) {
    int dir = blockIdx.y;
    int gw = (blockIdx.x * blockDim.x + threadIdx.x) >> 5;
    int lane = threadIdx.x & 31;
    if (gw >= n) return;
    const int* off = dir ? g_col_off : g_row_off;
    const int* nbr = dir ? g_csc_row : g_csr_col;
    const uint2* in = (const uint2*)(dir ? g_vz : g_uw);   // 32 uint2 per node row

    int s = off[gw], e = off[gw + 1];
    float a0 = 0.f, a1 = 0.f, a2 = 0.f, a3 = 0.f;
    for (int base = s; base < e; base += 32) {
        int idx = base + lane;
        int myn = 0;
        if (idx < e) myn = __ldg(nbr + idx);
        int cnt = min(32, e - base);
        for (int k = 0; k < cnt; k++) {
            int nd = __shfl_sync(0xffffffffu, myn, k);
            uint2 raw = __ldg(in + (size_t)nd * 32 + lane);
            __half2 h0 = *reinterpret_cast<__half2*>(&raw.x);
            __half2 h1 = *reinterpret_cast<__half2*>(&raw.y);
            float2 f0 = __half22float2(h0);
            float2 f1 = __half22float2(h1);
            a0 += f0.x; a1 += f0.y; a2 += f1.x; a3 += f1.y;
        }
    }
    bool partA = lane < 16;
    const float* post = dir ? (partA ? g_post[3] : g_post[5])
                            : (partA ? g_post[2] : g_post[4]);
    __half* outH = dir ? (partA ? g_Hh[3] : g_Hh[5])
                       : (partA ? g_Hh[2] : g_Hh[4]);
    float p = post[gw];
    int fbase = (lane & 15) * 4;
    __half2 o0 = __floats2half2_rn(p * a0, p * a1);
    __half2 o1 = __floats2half2_rn(p * a2, p * a3);
    uint2 st;
    st.x = *reinterpret_cast<uint32_t*>(&o0);
    st.y = *reinterpret_cast<uint32_t*>(&o1);
    *(uint2*)(outH + (size_t)gw * F + fbase) = st;
}

// ---------------- tf32 tensor-core GEMM (H exact in tf32, W hi+lo) -----------
// out = 0.75 * (sum_m H_m @ W_m + sum_m b_m)
__device__ __forceinline__ uint32_t f2tf(float x) {
    uint32_t r;
    asm("cvt.rna.tf32.f32 %0, %1;" : "=r"(r) : "f"(x));
    return r;
}

__device__ __forceinline__ void mma_tf32(float* c, uint32_t a0, uint32_t a1,
                                         uint32_t a2, uint32_t a3,
                                         uint32_t b0, uint32_t b1) {
    asm volatile(
        "mma.sync.aligned.m16n8k8.row.col.f32.tf32.tf32.f32 "
        "{%0,%1,%2,%3}, {%4,%5,%6,%7}, {%8,%9}, {%0,%1,%2,%3};"
        : "+f"(c[0]), "+f"(c[1]), "+f"(c[2]), "+f"(c[3])
        : "r"(a0), "r"(a1), "r"(a2), "r"(a3), "r"(b0), "r"(b1));
}

#define LDP 68   // padded smem leading dim

__global__ __launch_bounds__(256, 2) void k_gemm(
        const float* __restrict__ W0, const float* __restrict__ W1,
        const float* __restrict__ W2, const float* __restrict__ W3,
        const float* __restrict__ W4, const float* __restrict__ W5,
        const float* __restrict__ B0, const float* __restrict__ B1,
        const float* __restrict__ B2, const float* __restrict__ B3,
        const float* __restrict__ B4, const float* __restrict__ B5,
        float* __restrict__ out, int n) {
    __shared__ float sH[64 * LDP];    // H tile (converted from half), [row][k]
    __shared__ float sW[64 * LDP];    // W tile TRANSPOSED: [n][k]
    __shared__ float sBias[64];
    const float* Ws[6] = {W0, W1, W2, W3, W4, W5};
    const float* Bs[6] = {B0, B1, B2, B3, B4, B5};

    int tid = threadIdx.x;
    int rowBase = blockIdx.x * 64;
    int w = tid >> 5;
    int lane = tid & 31;
    int g = lane >> 2;
    int t = lane & 3;
    int wr = (w & 1) * 32;
    int wc = (w >> 1) * 16;

    if (tid < 64) {
        float s = 0.f;
#pragma unroll
        for (int m = 0; m < 6; m++) s += __ldg(Bs[m] + tid);
        sBias[tid] = s;
    }

    float acc[2][2][4];
#pragma unroll
    for (int i = 0; i < 2; i++)
#pragma unroll
        for (int j = 0; j < 2; j++)
#pragma unroll
            for (int q = 0; q < 4; q++) acc[i][j][q] = 0.f;

#pragma unroll
    for (int m = 0; m < 6; m++) {
        const __half* Hm = g_Hh[m];
        const float* Wm = Ws[m];
        // load H tile (64x64 half = 8KB): 256 thr x 4 x uint2 (4 halves)
#pragma unroll
        for (int it = 0; it < 4; it++) {
            int idx = tid + it * 256;        // uint2 index over 1024
            int r = idx >> 4;
            int c4 = (idx & 15) << 2;
            int gr = rowBase + r;
            uint2 raw = make_uint2(0u, 0u);
            if (gr < n) raw = __ldg((const uint2*)(Hm) + (size_t)gr * 16 + (idx & 15));
            __half2 h0 = *reinterpret_cast<__half2*>(&raw.x);
            __half2 h1 = *reinterpret_cast<__half2*>(&raw.y);
            float2 f0 = __half22float2(h0);
            float2 f1 = __half22float2(h1);
            *(float4*)(&sH[r * LDP + c4]) = make_float4(f0.x, f0.y, f1.x, f1.y);
        }
        // load W transposed: sW[nn][k] = W[k][nn]
#pragma unroll
        for (int it = 0; it < 4; it++) {
            int idx = tid + it * 256;
            int k = idx >> 4;
            int c4 = (idx & 15) << 2;
            float4 val = __ldg((const float4*)(Wm + k * 64 + c4));
            sW[(c4 + 0) * LDP + k] = val.x;
            sW[(c4 + 1) * LDP + k] = val.y;
            sW[(c4 + 2) * LDP + k] = val.z;
            sW[(c4 + 3) * LDP + k] = val.w;
        }
        __syncthreads();

#pragma unroll
        for (int kk = 0; kk < 64; kk += 8) {
            uint32_t a[2][4];
#pragma unroll
            for (int mt = 0; mt < 2; mt++) {
                int rbase = wr + mt * 16;
                a[mt][0] = f2tf(sH[(rbase + g) * LDP + kk + t]);        // exact (half source)
                a[mt][1] = f2tf(sH[(rbase + g + 8) * LDP + kk + t]);
                a[mt][2] = f2tf(sH[(rbase + g) * LDP + kk + t + 4]);
                a[mt][3] = f2tf(sH[(rbase + g + 8) * LDP + kk + t + 4]);
            }
            uint32_t bhi[2][2], blo[2][2];
#pragma unroll
            for (int nt = 0; nt < 2; nt++) {
                int nbase = wc + nt * 8;
                float f0 = sW[(nbase + g) * LDP + kk + t];
                float f1 = sW[(nbase + g) * LDP + kk + t + 4];
                bhi[nt][0] = f2tf(f0); blo[nt][0] = f2tf(f0 - __uint_as_float(bhi[nt][0]));
                bhi[nt][1] = f2tf(f1); blo[nt][1] = f2tf(f1 - __uint_as_float(bhi[nt][1]));
            }
#pragma unroll
            for (int mt = 0; mt < 2; mt++)
#pragma unroll
                for (int nt = 0; nt < 2; nt++) {
                    mma_tf32(acc[mt][nt], a[mt][0], a[mt][1], a[mt][2], a[mt][3],
                             blo[nt][0], blo[nt][1]);
                    mma_tf32(acc[mt][nt], a[mt][0], a[mt][1], a[mt][2], a[mt][3],
                             bhi[nt][0], bhi[nt][1]);
                }
        }
        __syncthreads();
    }

#pragma unroll
    for (int mt = 0; mt < 2; mt++) {
#pragma unroll
        for (int nt = 0; nt < 2; nt++) {
            int col = wc + nt * 8 + 2 * t;
            float bx = sBias[col], by = sBias[col + 1];
            int r1 = rowBase + wr + mt * 16 + g;
            int r2 = r1 + 8;
            if (r1 < n) {
                float2 o;
                o.x = 0.75f * (acc[mt][nt][0] + bx);
                o.y = 0.75f * (acc[mt][nt][1] + by);
                *(float2*)(out + (size_t)r1 * 64 + col) = o;
            }
            if (r2 < n) {
                float2 o;
                o.x = 0.75f * (acc[mt][nt][2] + bx);
                o.y = 0.75f * (acc[mt][nt][3] + by);
                *(float2*)(out + (size_t)r2 * 64 + col) = o;
            }
        }
    }
}

// ---------------- launcher ----------------
extern "C" void kernel_launch(void* const* d_in, const int* in_sizes, int n_in,
                              void* d_out, int out_size) {
    const float* x = (const float*)d_in[0];
    const int* ei = (const int*)d_in[1];
    const float* W0 = (const float*)d_in[2],  *B0 = (const float*)d_in[3];
    const float* W1 = (const float*)d_in[4],  *B1 = (const float*)d_in[5];
    const float* W2 = (const float*)d_in[6],  *B2 = (const float*)d_in[7];
    const float* W3 = (const float*)d_in[8],  *B3 = (const float*)d_in[9];
    const float* W4 = (const float*)d_in[10], *B4 = (const float*)d_in[11];
    const float* W5 = (const float*)d_in[12], *B5 = (const float*)d_in[13];
    float* out = (float*)d_out;

    int n = in_sizes[0] / F;
    int E = in_sizes[1] / 2;
    if (n > NN) n = NN;
    if (E > EE) E = EE;

    int nb = (n + 255) / 256;
    int eb = (E + 255) / 256;
    int pb = (n + SCAN_B - 1) / SCAN_B;

    k_zero<<<nb, 256>>>(n);
    k_hist<<<eb, 256>>>(ei, E);
    k_scan_part<<<dim3(pb, 2), 256>>>(n);
    k_scan_mid<<<1, 128>>>(pb);
    k_scan_final<<<dim3(pb, 2), SCAN_B>>>(n, pb);
    k_scatter<<<eb, 256>>>(ei, E);
    k_degspmv<<<dim3(nb, 2), 256>>>(n);
    k_scales<<<nb, 256>>>(n);

    int sb = (n + 7) / 8;   // warp-per-node, 8 warps/block
    k_spmm3<<<dim3(sb, 2), 256>>>(x, n);
    k_spmm2<<<dim3(sb, 2), 256>>>(n);

    int gb = (n + 63) / 64;
    k_gemm<<<gb, 256>>>(W0, W1, W2, W3, W4, W5,
                        B0, B1, B2, B3, B4, B5, out, n);
}

// round 5
// speedup vs baseline: 1.7886x; 1.0573x over previous
#include <cuda_runtime.h>
#include <cuda_fp16.h>
#include <cstdint>

#define NN 100000
#define EE 1600000
#define F 64
#define SCAN_B 1024
#define MAXPB 128   // ceil(NN/1024) = 98 <= 128

// ---------------- device scratch (static: allocation-guard safe) ----------------
__device__ int   g_cnt_row[NN];
__device__ int   g_cnt_col[NN];
__device__ int   g_row_off[NN + 1];
__device__ int   g_col_off[NN + 1];
__device__ int   g_cur_row[NN];
__device__ int   g_cur_col[NN];
__device__ int   g_part[2][MAXPB];
__device__ int   g_partscan[2][MAXPB + 1];
__device__ int   g_csr_col[EE];   // neighbors (col ids) grouped by row  -> Av
__device__ int   g_csc_row[EE];   // neighbors (row ids) grouped by col  -> Atv
__device__ float g_Avdin[NN], g_Avdout[NN], g_Atvdout[NN], g_Atvdin[NN];
__device__ float4 g_preA[NN];     // {isi, sAtA, sAAi, 0} pre-scales for round-1 Av
__device__ float4 g_preT[NN];     // {iso, sAAt, sAAo, 0} pre-scales for round-1 Atv
__device__ float g_post[6][NN];   // 0:iso 1:isi 2:sAAt 3:sAtA 4:sAAo 5:sAAi
__device__ __half g_xh[(size_t)NN * F];     // fp16 copy of x (128B/row)
// packed fp16 intermediates: per node 128 halves (256B)
__device__ __half g_uw[(size_t)NN * 128];   // [u | w]
__device__ __half g_vz[(size_t)NN * 128];   // [v | z]
__device__ __half g_Hh[6][(size_t)NN * F];  // A_x, At_x, AAt_x, AtA_x, AA_x, AtAt_x

// ---------------- CSR/CSC build ----------------
__global__ void k_zero(int n) {
    int i = blockIdx.x * blockDim.x + threadIdx.x;
    if (i < n) { g_cnt_row[i] = 0; g_cnt_col[i] = 0; }
}

__global__ void k_hist(const int* __restrict__ ei, int E) {
    int e = blockIdx.x * blockDim.x + threadIdx.x;
    if (e < E) {
        atomicAdd(&g_cnt_row[ei[e]], 1);
        atomicAdd(&g_cnt_col[ei[E + e]], 1);
    }
}

__global__ void k_xhalf(const float* __restrict__ x, int total32) {
    int i = blockIdx.x * blockDim.x + threadIdx.x;   // over n*32 words
    if (i < total32) {
        float2 f = __ldg((const float2*)x + i);
        *((__half2*)g_xh + i) = __floats2half2_rn(f.x, f.y);
    }
}

// -------- multi-block exclusive scan: phase 1, per-block partial sums --------
__global__ void k_scan_part(int n) {
    int dir = blockIdx.y;
    const int* cnt = dir ? g_cnt_col : g_cnt_row;
    __shared__ int sh[256];
    int tid = threadIdx.x;
    int base = blockIdx.x * SCAN_B;
    int s = 0;
#pragma unroll
    for (int j = 0; j < 4; j++) {
        int i = base + tid + j * 256;
        if (i < n) s += cnt[i];
    }
    sh[tid] = s;
    __syncthreads();
    for (int d = 128; d > 0; d >>= 1) {
        if (tid < d) sh[tid] += sh[tid + d];
        __syncthreads();
    }
    if (tid == 0) g_part[dir][blockIdx.x] = sh[0];
}

// -------- phase 2: single block scans the <=128 partials for both dirs -------
__global__ void k_scan_mid(int pb) {
    __shared__ int sh[128];
    int tid = threadIdx.x;
    for (int dir = 0; dir < 2; dir++) {
        int v = (tid < pb) ? g_part[dir][tid] : 0;
        sh[tid] = v;
        __syncthreads();
        for (int d = 1; d < 128; d <<= 1) {
            int add = (tid >= d) ? sh[tid - d] : 0;
            __syncthreads();
            sh[tid] += add;
            __syncthreads();
        }
        if (tid < pb) g_partscan[dir][tid] = sh[tid] - v;   // exclusive
        if (tid == 0) g_partscan[dir][pb] = sh[127];        // total
        __syncthreads();
    }
}

// -------- phase 3: per-block scan + base; also init scatter cursors ----------
__global__ void k_scan_final(int n, int pb) {
    int dir = blockIdx.y;
    const int* cnt = dir ? g_cnt_col : g_cnt_row;
    int* off = dir ? g_col_off : g_row_off;
    int* cur = dir ? g_cur_col : g_cur_row;
    __shared__ int sh[SCAN_B];
    int tid = threadIdx.x;
    int i = blockIdx.x * SCAN_B + tid;
    int v = (i < n) ? cnt[i] : 0;
    sh[tid] = v;
    __syncthreads();
    for (int d = 1; d < SCAN_B; d <<= 1) {
        int add = (tid >= d) ? sh[tid - d] : 0;
        __syncthreads();
        sh[tid] += add;
        __syncthreads();
    }
    if (i < n) {
        int o = g_partscan[dir][blockIdx.x] + sh[tid] - v;  // exclusive
        off[i] = o;
        cur[i] = o;
    }
    if (blockIdx.x == 0 && tid == 0) off[n] = g_partscan[dir][pb];
}

__global__ void k_scatter(const int* __restrict__ ei, int E) {
    int e = blockIdx.x * blockDim.x + threadIdx.x;
    if (e < E) {
        int r = ei[e], c = ei[E + e];
        int p = atomicAdd(&g_cur_row[r], 1);
        g_csr_col[p] = c;
        int q = atomicAdd(&g_cur_col[c], 1);
        g_csc_row[q] = r;
    }
}

// ---------------- scalar degree SpMVs (both per direction in one pass) -------
__global__ void k_degspmv(int n) {
    int dir = blockIdx.y;
    int i = blockIdx.x * blockDim.x + threadIdx.x;
    if (i >= n) return;
    const int* off = dir ? g_col_off : g_row_off;
    const int* nbr = dir ? g_csc_row : g_csr_col;
    const int* cA  = dir ? g_cnt_row : g_cnt_col;
    const int* cB  = dir ? g_cnt_col : g_cnt_row;
    float* oA = dir ? g_Atvdout : g_Avdin;
    float* oB = dir ? g_Atvdin  : g_Avdout;
    int s = off[i], e = off[i + 1];
    int sa = 0, sb = 0;
    for (int j = s; j < e; j++) {
        int nb = __ldg(nbr + j);
        sa += __ldg(cA + nb);
        sb += __ldg(cB + nb);
    }
    oA[i] = (float)sa;
    oB[i] = (float)sb;
}

__device__ __forceinline__ float invsq(float d) {
    return d > 0.f ? 1.0f / sqrtf(d) : 0.0f;
}

__global__ void k_scales(int n) {
    int i = blockIdx.x * blockDim.x + threadIdx.x;
    if (i >= n) return;
    float iso  = invsq((float)g_cnt_row[i]);
    float isi  = invsq((float)g_cnt_col[i]);
    float sAAt = invsq(g_Avdin[i]);
    float sAtA = invsq(g_Atvdout[i]);
    float sAAo = invsq(g_Avdout[i]);
    float sAAi = invsq(g_Atvdin[i]);
    g_preA[i] = make_float4(isi, sAtA, sAAi, 0.f);
    g_preT[i] = make_float4(iso, sAAt, sAAo, 0.f);
    g_post[0][i] = iso;  g_post[1][i] = isi;
    g_post[2][i] = sAAt; g_post[3][i] = sAtA;
    g_post[4][i] = sAAo; g_post[5][i] = sAAi;
}

// ---------------- round-1 fused SpMM over fp16 x: MLP-4 batched gather -------
// dir0 (Av):  H0 (post iso), v -> g_vz[0:64],  w -> g_uw[64:128]   pre={isi,sAtA,sAAi}
// dir1 (Atv): H1 (post isi), u -> g_uw[0:64],  z -> g_vz[64:128]   pre={iso,sAAt,sAAo}
__global__ void k_spmm3(int n) {
    int dir = blockIdx.y;
    int gw = (blockIdx.x * blockDim.x + threadIdx.x) >> 5;
    int lane = threadIdx.x & 31;
    if (gw >= n) return;
    const int* off = dir ? g_col_off : g_row_off;
    const int* nbr = dir ? g_csc_row : g_csr_col;
    const float4* pre = dir ? g_preT : g_preA;
    const float* post0 = dir ? g_post[1] : g_post[0];
    __half* out0 = g_Hh[dir];
    __half* out1 = dir ? g_uw : g_vz;
    __half* out2 = dir ? g_vz : g_uw;
    const uint32_t* xw = (const uint32_t*)g_xh;   // 32 words per node row

    int s = off[gw], e = off[gw + 1];
    float a0x = 0.f, a0y = 0.f, a1x = 0.f, a1y = 0.f, a2x = 0.f, a2y = 0.f;
    for (int base = s; base < e; base += 32) {
        int idx = base + lane;
        int myn = 0;
        float4 mp = make_float4(0.f, 0.f, 0.f, 0.f);
        if (idx < e) {
            myn = __ldg(nbr + idx);
            mp = __ldg(pre + myn);
        }
        int cnt = min(32, e - base);
        for (int k = 0; k < cnt; k += 4) {
            int nd[4]; float p0[4], p1[4], p2[4]; uint32_t raw[4];
#pragma unroll
            for (int j = 0; j < 4; j++) {
                int kk = k + j;                       // kk<=31 always; mp=0 beyond cnt
                nd[j] = __shfl_sync(0xffffffffu, myn, kk);
                p0[j] = __shfl_sync(0xffffffffu, mp.x, kk);
                p1[j] = __shfl_sync(0xffffffffu, mp.y, kk);
                p2[j] = __shfl_sync(0xffffffffu, mp.z, kk);
            }
#pragma unroll
            for (int j = 0; j < 4; j++)
                raw[j] = __ldg(xw + (size_t)nd[j] * 32 + lane);
#pragma unroll
            for (int j = 0; j < 4; j++) {
                float2 f = __half22float2(*reinterpret_cast<__half2*>(&raw[j]));
                a0x = fmaf(p0[j], f.x, a0x); a0y = fmaf(p0[j], f.y, a0y);
                a1x = fmaf(p1[j], f.x, a1x); a1y = fmaf(p1[j], f.y, a1y);
                a2x = fmaf(p2[j], f.x, a2x); a2y = fmaf(p2[j], f.y, a2y);
            }
        }
    }
    float pp = post0[gw];
    *(__half2*)(out0 + (size_t)gw * F + lane * 2) = __floats2half2_rn(pp * a0x, pp * a0y);
    *(__half2*)(out1 + (size_t)gw * 128 + lane * 2) = __floats2half2_rn(a1x, a1y);
    *(__half2*)(out2 + (size_t)gw * 128 + 64 + lane * 2) = __floats2half2_rn(a2x, a2y);
}

// ---------------- round-2 fused SpMM: MLP-4 batched 256B gathers -------------
// dir0 (Av over g_uw):  lanes 0-15 u -> H2 (sAAt), lanes 16-31 w -> H4 (sAAo)
// dir1 (Atv over g_vz): lanes 0-15 v -> H3 (sAtA), lanes 16-31 z -> H5 (sAAi)
__global__ void k_spmm2(int n) {
    int dir = blockIdx.y;
    int gw = (blockIdx.x * blockDim.x + threadIdx.x) >> 5;
    int lane = threadIdx.x & 31;
    if (gw >= n) return;
    const int* off = dir ? g_col_off : g_row_off;
    const int* nbr = dir ? g_csc_row : g_csr_col;
    const uint2* in = (const uint2*)(dir ? g_vz : g_uw);

    int s = off[gw], e = off[gw + 1];
    float a0 = 0.f, a1 = 0.f, a2 = 0.f, a3 = 0.f;
    for (int base = s; base < e; base += 32) {
        int idx = base + lane;
        int myn = 0;
        float wt = 0.f;
        if (idx < e) { myn = __ldg(nbr + idx); wt = 1.f; }
        int cnt = min(32, e - base);
        for (int k = 0; k < cnt; k += 4) {
            int nd[4]; float wj[4]; uint2 raw[4];
#pragma unroll
            for (int j = 0; j < 4; j++) {
                int kk = k + j;                       // wt=0 beyond cnt -> contributes 0
                nd[j] = __shfl_sync(0xffffffffu, myn, kk);
                wj[j] = __shfl_sync(0xffffffffu, wt, kk);
            }
#pragma unroll
            for (int j = 0; j < 4; j++)
                raw[j] = __ldg(in + (size_t)nd[j] * 32 + lane);
#pragma unroll
            for (int j = 0; j < 4; j++) {
                float2 f0 = __half22float2(*reinterpret_cast<__half2*>(&raw[j].x));
                float2 f1 = __half22float2(*reinterpret_cast<__half2*>(&raw[j].y));
                a0 = fmaf(wj[j], f0.x, a0); a1 = fmaf(wj[j], f0.y, a1);
                a2 = fmaf(wj[j], f1.x, a2); a3 = fmaf(wj[j], f1.y, a3);
            }
        }
    }
    bool partA = lane < 16;
    const float* post = dir ? (partA ? g_post[3] : g_post[5])
                            : (partA ? g_post[2] : g_post[4]);
    __half* outH = dir ? (partA ? g_Hh[3] : g_Hh[5])
                       : (partA ? g_Hh[2] : g_Hh[4]);
    float p = post[gw];
    int fbase = (lane & 15) * 4;
    __half2 o0 = __floats2half2_rn(p * a0, p * a1);
    __half2 o1 = __floats2half2_rn(p * a2, p * a3);
    uint2 st;
    st.x = *reinterpret_cast<uint32_t*>(&o0);
    st.y = *reinterpret_cast<uint32_t*>(&o1);
    *(uint2*)(outH + (size_t)gw * F + fbase) = st;
}

// ---------------- tf32 tensor-core GEMM (H exact in tf32, W hi+lo) -----------
__device__ __forceinline__ uint32_t f2tf(float x) {
    uint32_t r;
    asm("cvt.rna.tf32.f32 %0, %1;" : "=r"(r) : "f"(x));
    return r;
}

__device__ __forceinline__ void mma_tf32(float* c, uint32_t a0, uint32_t a1,
                                         uint32_t a2, uint32_t a3,
                                         uint32_t b0, uint32_t b1) {
    asm volatile(
        "mma.sync.aligned.m16n8k8.row.col.f32.tf32.tf32.f32 "
        "{%0,%1,%2,%3}, {%4,%5,%6,%7}, {%8,%9}, {%0,%1,%2,%3};"
        : "+f"(c[0]), "+f"(c[1]), "+f"(c[2]), "+f"(c[3])
        : "r"(a0), "r"(a1), "r"(a2), "r"(a3), "r"(b0), "r"(b1));
}

#define LDP 68

__global__ __launch_bounds__(256, 2) void k_gemm(
        const float* __restrict__ W0, const float* __restrict__ W1,
        const float* __restrict__ W2, const float* __restrict__ W3,
        const float* __restrict__ W4, const float* __restrict__ W5,
        const float* __restrict__ B0, const float* __restrict__ B1,
        const float* __restrict__ B2, const float* __restrict__ B3,
        const float* __restrict__ B4, const float* __restrict__ B5,
        float* __restrict__ out, int n) {
    __shared__ float sH[64 * LDP];
    __shared__ float sW[64 * LDP];
    __shared__ float sBias[64];
    const float* Ws[6] = {W0, W1, W2, W3, W4, W5};
    const float* Bs[6] = {B0, B1, B2, B3, B4, B5};

    int tid = threadIdx.x;
    int rowBase = blockIdx.x * 64;
    int w = tid >> 5;
    int lane = tid & 31;
    int g = lane >> 2;
    int t = lane & 3;
    int wr = (w & 1) * 32;
    int wc = (w >> 1) * 16;

    if (tid < 64) {
        float s = 0.f;
#pragma unroll
        for (int m = 0; m < 6; m++) s += __ldg(Bs[m] + tid);
        sBias[tid] = s;
    }

    float acc[2][2][4];
#pragma unroll
    for (int i = 0; i < 2; i++)
#pragma unroll
        for (int j = 0; j < 2; j++)
#pragma unroll
            for (int q = 0; q < 4; q++) acc[i][j][q] = 0.f;

#pragma unroll
    for (int m = 0; m < 6; m++) {
        const __half* Hm = g_Hh[m];
        const float* Wm = Ws[m];
#pragma unroll
        for (int it = 0; it < 4; it++) {
            int idx = tid + it * 256;
            int r = idx >> 4;
            int c4 = (idx & 15) << 2;
            int gr = rowBase + r;
            uint2 raw = make_uint2(0u, 0u);
            if (gr < n) raw = __ldg((const uint2*)(Hm) + (size_t)gr * 16 + (idx & 15));
            __half2 h0 = *reinterpret_cast<__half2*>(&raw.x);
            __half2 h1 = *reinterpret_cast<__half2*>(&raw.y);
            float2 f0 = __half22float2(h0);
            float2 f1 = __half22float2(h1);
            *(float4*)(&sH[r * LDP + c4]) = make_float4(f0.x, f0.y, f1.x, f1.y);
        }
#pragma unroll
        for (int it = 0; it < 4; it++) {
            int idx = tid + it * 256;
            int k = idx >> 4;
            int c4 = (idx & 15) << 2;
            float4 val = __ldg((const float4*)(Wm + k * 64 + c4));
            sW[(c4 + 0) * LDP + k] = val.x;
            sW[(c4 + 1) * LDP + k] = val.y;
            sW[(c4 + 2) * LDP + k] = val.z;
            sW[(c4 + 3) * LDP + k] = val.w;
        }
        __syncthreads();

#pragma unroll
        for (int kk = 0; kk < 64; kk += 8) {
            uint32_t a[2][4];
#pragma unroll
            for (int mt = 0; mt < 2; mt++) {
                int rbase = wr + mt * 16;
                a[mt][0] = f2tf(sH[(rbase + g) * LDP + kk + t]);
                a[mt][1] = f2tf(sH[(rbase + g + 8) * LDP + kk + t]);
                a[mt][2] = f2tf(sH[(rbase + g) * LDP + kk + t + 4]);
                a[mt][3] = f2tf(sH[(rbase + g + 8) * LDP + kk + t + 4]);
            }
            uint32_t bhi[2][2], blo[2][2];
#pragma unroll
            for (int nt = 0; nt < 2; nt++) {
                int nbase = wc + nt * 8;
                float f0 = sW[(nbase + g) * LDP + kk + t];
                float f1 = sW[(nbase + g) * LDP + kk + t + 4];
                bhi[nt][0] = f2tf(f0); blo[nt][0] = f2tf(f0 - __uint_as_float(bhi[nt][0]));
                bhi[nt][1] = f2tf(f1); blo[nt][1] = f2tf(f1 - __uint_as_float(bhi[nt][1]));
            }
#pragma unroll
            for (int mt = 0; mt < 2; mt++)
#pragma unroll
                for (int nt = 0; nt < 2; nt++) {
                    mma_tf32(acc[mt][nt], a[mt][0], a[mt][1], a[mt][2], a[mt][3],
                             blo[nt][0], blo[nt][1]);
                    mma_tf32(acc[mt][nt], a[mt][0], a[mt][1], a[mt][2], a[mt][3],
                             bhi[nt][0], bhi[nt][1]);
                }
        }
        __syncthreads();
    }

#pragma unroll
    for (int mt = 0; mt < 2; mt++) {
#pragma unroll
        for (int nt = 0; nt < 2; nt++) {
            int col = wc + nt * 8 + 2 * t;
            float bx = sBias[col], by = sBias[col + 1];
            int r1 = rowBase + wr + mt * 16 + g;
            int r2 = r1 + 8;
            if (r1 < n) {
                float2 o;
                o.x = 0.75f * (acc[mt][nt][0] + bx);
                o.y = 0.75f * (acc[mt][nt][1] + by);
                *(float2*)(out + (size_t)r1 * 64 + col) = o;
            }
            if (r2 < n) {
                float2 o;
                o.x = 0.75f * (acc[mt][nt][2] + bx);
                o.y = 0.75f * (acc[mt][nt][3] + by);
                *(float2*)(out + (size_t)r2 * 64 + col) = o;
            }
        }
    }
}

// ---------------- launcher ----------------
extern "C" void kernel_launch(void* const* d_in, const int* in_sizes, int n_in,
                              void* d_out, int out_size) {
    const float* x = (const float*)d_in[0];
    const int* ei = (const int*)d_in[1];
    const float* W0 = (const float*)d_in[2],  *B0 = (const float*)d_in[3];
    const float* W1 = (const float*)d_in[4],  *B1 = (const float*)d_in[5];
    const float* W2 = (const float*)d_in[6],  *B2 = (const float*)d_in[7];
    const float* W3 = (const float*)d_in[8],  *B3 = (const float*)d_in[9];
    const float* W4 = (const float*)d_in[10], *B4 = (const float*)d_in[11];
    const float* W5 = (const float*)d_in[12], *B5 = (const float*)d_in[13];
    float* out = (float*)d_out;

    int n = in_sizes[0] / F;
    int E = in_sizes[1] / 2;
    if (n > NN) n = NN;
    if (E > EE) E = EE;

    int nb = (n + 255) / 256;
    int eb = (E + 255) / 256;
    int pb = (n + SCAN_B - 1) / SCAN_B;
    int xw = n * 32;                       // half2 words in x

    k_zero<<<nb, 256>>>(n);
    k_hist<<<eb, 256>>>(ei, E);
    k_xhalf<<<(xw + 255) / 256, 256>>>(x, xw);
    k_scan_part<<<dim3(pb, 2), 256>>>(n);
    k_scan_mid<<<1, 128>>>(pb);
    k_scan_final<<<dim3(pb, 2), SCAN_B>>>(n, pb);
    k_scatter<<<eb, 256>>>(ei, E);
    k_degspmv<<<dim3(nb, 2), 256>>>(n);
    k_scales<<<nb, 256>>>(n);

    int sb = (n + 7) / 8;   // warp-per-node, 8 warps/block
    k_spmm3<<<dim3(sb, 2), 256>>>(n);
    k_spmm2<<<dim3(sb, 2), 256>>>(n);

    int gb = (n + 63) / 64;
    k_gemm<<<gb, 256>>>(W0, W1, W2, W3, W4, W5,
                        B0, B1, B2, B3, B4, B5, out, n);
}

// round 6
// speedup vs baseline: 1.9155x; 1.0710x over previous
#include <cuda_runtime.h>
#include <cuda_fp16.h>
#include <cstdint>

#define NN 100000
#define EE 1600000
#define F 64
#define SCAN_B 1024
#define MAXPB 128   // ceil(NN/1024) = 98 <= 128

// ---------------- device scratch (static: allocation-guard safe) ----------------
__device__ int   g_cnt_row[NN];
__device__ int   g_cnt_col[NN];
__device__ int   g_row_off[NN + 1];
__device__ int   g_col_off[NN + 1];
__device__ int   g_cur_row[NN];
__device__ int   g_cur_col[NN];
__device__ int   g_part[2][MAXPB];
__device__ int   g_partscan[2][MAXPB + 1];
__device__ int   g_csr_col[EE];   // neighbors (col ids) grouped by row  -> Av
__device__ int   g_csc_row[EE];   // neighbors (row ids) grouped by col  -> Atv
__device__ float g_Avdin[NN], g_Avdout[NN], g_Atvdout[NN], g_Atvdin[NN];
__device__ float4 g_preA[NN];     // {isi, sAtA, sAAi, 0} pre-scales for round-1 Av
__device__ float4 g_preT[NN];     // {iso, sAAt, sAAo, 0} pre-scales for round-1 Atv
__device__ float g_post[6][NN];   // 0:iso 1:isi 2:sAAt 3:sAtA 4:sAAo 5:sAAi
__device__ __half g_xh[(size_t)NN * F];     // fp16 copy of x (128B/row)
__device__ __half g_uw[(size_t)NN * 128];   // [u | w]
__device__ __half g_vz[(size_t)NN * 128];   // [v | z]
__device__ __half g_Hh[6][(size_t)NN * F];  // A_x, At_x, AAt_x, AtA_x, AA_x, AtAt_x

// ---------------- x -> fp16 copy, fused with counter zeroing ----------------
__global__ void k_xhalf(const float* __restrict__ x, int total32, int n) {
    int i = blockIdx.x * blockDim.x + threadIdx.x;
    if (i < n) { g_cnt_row[i] = 0; g_cnt_col[i] = 0; }
    if (i < total32) {
        float2 f = __ldg((const float2*)x + i);
        *((__half2*)g_xh + i) = __floats2half2_rn(f.x, f.y);
    }
}

__global__ void k_hist(const int* __restrict__ ei, int E) {
    int e = blockIdx.x * blockDim.x + threadIdx.x;
    if (e < E) {
        atomicAdd(&g_cnt_row[ei[e]], 1);
        atomicAdd(&g_cnt_col[ei[E + e]], 1);
    }
}

// -------- multi-block exclusive scan: phase 1, per-block partial sums --------
__global__ void k_scan_part(int n) {
    int dir = blockIdx.y;
    const int* cnt = dir ? g_cnt_col : g_cnt_row;
    __shared__ int sh[256];
    int tid = threadIdx.x;
    int base = blockIdx.x * SCAN_B;
    int s = 0;
#pragma unroll
    for (int j = 0; j < 4; j++) {
        int i = base + tid + j * 256;
        if (i < n) s += cnt[i];
    }
    sh[tid] = s;
    __syncthreads();
    for (int d = 128; d > 0; d >>= 1) {
        if (tid < d) sh[tid] += sh[tid + d];
        __syncthreads();
    }
    if (tid == 0) g_part[dir][blockIdx.x] = sh[0];
}

// -------- phase 2: single block scans the <=128 partials for both dirs -------
__global__ void k_scan_mid(int pb) {
    __shared__ int sh[128];
    int tid = threadIdx.x;
    for (int dir = 0; dir < 2; dir++) {
        int v = (tid < pb) ? g_part[dir][tid] : 0;
        sh[tid] = v;
        __syncthreads();
        for (int d = 1; d < 128; d <<= 1) {
            int add = (tid >= d) ? sh[tid - d] : 0;
            __syncthreads();
            sh[tid] += add;
            __syncthreads();
        }
        if (tid < pb) g_partscan[dir][tid] = sh[tid] - v;   // exclusive
        if (tid == 0) g_partscan[dir][pb] = sh[127];        // total
        __syncthreads();
    }
}

// -------- phase 3: per-block scan + base; also init scatter cursors ----------
__global__ void k_scan_final(int n, int pb) {
    int dir = blockIdx.y;
    const int* cnt = dir ? g_cnt_col : g_cnt_row;
    int* off = dir ? g_col_off : g_row_off;
    int* cur = dir ? g_cur_col : g_cur_row;
    __shared__ int sh[SCAN_B];
    int tid = threadIdx.x;
    int i = blockIdx.x * SCAN_B + tid;
    int v = (i < n) ? cnt[i] : 0;
    sh[tid] = v;
    __syncthreads();
    for (int d = 1; d < SCAN_B; d <<= 1) {
        int add = (tid >= d) ? sh[tid - d] : 0;
        __syncthreads();
        sh[tid] += add;
        __syncthreads();
    }
    if (i < n) {
        int o = g_partscan[dir][blockIdx.x] + sh[tid] - v;  // exclusive
        off[i] = o;
        cur[i] = o;
    }
    if (blockIdx.x == 0 && tid == 0) off[n] = g_partscan[dir][pb];
}

__global__ void k_scatter(const int* __restrict__ ei, int E) {
    int e = blockIdx.x * blockDim.x + threadIdx.x;
    if (e < E) {
        int r = ei[e], c = ei[E + e];
        int p = atomicAdd(&g_cur_row[r], 1);
        g_csr_col[p] = c;
        int q = atomicAdd(&g_cur_col[c], 1);
        g_csc_row[q] = r;
    }
}

// ---------------- scalar degree SpMVs, MLP-4 unrolled -------------------------
__global__ void k_degspmv(int n) {
    int dir = blockIdx.y;
    int i = blockIdx.x * blockDim.x + threadIdx.x;
    if (i >= n) return;
    const int* off = dir ? g_col_off : g_row_off;
    const int* nbr = dir ? g_csc_row : g_csr_col;
    const int* cA  = dir ? g_cnt_row : g_cnt_col;
    const int* cB  = dir ? g_cnt_col : g_cnt_row;
    float* oA = dir ? g_Atvdout : g_Avdin;
    float* oB = dir ? g_Atvdin  : g_Avdout;
    int s = off[i], e = off[i + 1];
    int sa = 0, sb = 0;
    int j = s;
    for (; j + 4 <= e; j += 4) {
        int n0 = __ldg(nbr + j + 0);
        int n1 = __ldg(nbr + j + 1);
        int n2 = __ldg(nbr + j + 2);
        int n3 = __ldg(nbr + j + 3);
        int a0 = __ldg(cA + n0), b0 = __ldg(cB + n0);
        int a1 = __ldg(cA + n1), b1 = __ldg(cB + n1);
        int a2 = __ldg(cA + n2), b2 = __ldg(cB + n2);
        int a3 = __ldg(cA + n3), b3 = __ldg(cB + n3);
        sa += (a0 + a1) + (a2 + a3);
        sb += (b0 + b1) + (b2 + b3);
    }
    for (; j < e; j++) {
        int nb = __ldg(nbr + j);
        sa += __ldg(cA + nb);
        sb += __ldg(cB + nb);
    }
    oA[i] = (float)sa;
    oB[i] = (float)sb;
}

__device__ __forceinline__ float invsq(float d) {
    return d > 0.f ? 1.0f / sqrtf(d) : 0.0f;
}

__global__ void k_scales(int n) {
    int i = blockIdx.x * blockDim.x + threadIdx.x;
    if (i >= n) return;
    float iso  = invsq((float)g_cnt_row[i]);
    float isi  = invsq((float)g_cnt_col[i]);
    float sAAt = invsq(g_Avdin[i]);
    float sAtA = invsq(g_Atvdout[i]);
    float sAAo = invsq(g_Avdout[i]);
    float sAAi = invsq(g_Atvdin[i]);
    g_preA[i] = make_float4(isi, sAtA, sAAi, 0.f);
    g_preT[i] = make_float4(iso, sAAt, sAAo, 0.f);
    g_post[0][i] = iso;  g_post[1][i] = isi;
    g_post[2][i] = sAAt; g_post[3][i] = sAtA;
    g_post[4][i] = sAAo; g_post[5][i] = sAAi;
}

// ---------------- round-1 fused SpMM over fp16 x: MLP-4 batched gather -------
__global__ void k_spmm3(int n) {
    int dir = blockIdx.y;
    int gw = (blockIdx.x * blockDim.x + threadIdx.x) >> 5;
    int lane = threadIdx.x & 31;
    if (gw >= n) return;
    const int* off = dir ? g_col_off : g_row_off;
    const int* nbr = dir ? g_csc_row : g_csr_col;
    const float4* pre = dir ? g_preT : g_preA;
    const float* post0 = dir ? g_post[1] : g_post[0];
    __half* out0 = g_Hh[dir];
    __half* out1 = dir ? g_uw : g_vz;
    __half* out2 = dir ? g_vz : g_uw;
    const uint32_t* xw = (const uint32_t*)g_xh;

    int s = off[gw], e = off[gw + 1];
    float a0x = 0.f, a0y = 0.f, a1x = 0.f, a1y = 0.f, a2x = 0.f, a2y = 0.f;
    for (int base = s; base < e; base += 32) {
        int idx = base + lane;
        int myn = 0;
        float4 mp = make_float4(0.f, 0.f, 0.f, 0.f);
        if (idx < e) {
            myn = __ldg(nbr + idx);
            mp = __ldg(pre + myn);
        }
        int cnt = min(32, e - base);
        for (int k = 0; k < cnt; k += 4) {
            int nd[4]; float p0[4], p1[4], p2[4]; uint32_t raw[4];
#pragma unroll
            for (int j = 0; j < 4; j++) {
                int kk = k + j;
                nd[j] = __shfl_sync(0xffffffffu, myn, kk);
                p0[j] = __shfl_sync(0xffffffffu, mp.x, kk);
                p1[j] = __shfl_sync(0xffffffffu, mp.y, kk);
                p2[j] = __shfl_sync(0xffffffffu, mp.z, kk);
            }
#pragma unroll
            for (int j = 0; j < 4; j++)
                raw[j] = __ldg(xw + (size_t)nd[j] * 32 + lane);
#pragma unroll
            for (int j = 0; j < 4; j++) {
                float2 f = __half22float2(*reinterpret_cast<__half2*>(&raw[j]));
                a0x = fmaf(p0[j], f.x, a0x); a0y = fmaf(p0[j], f.y, a0y);
                a1x = fmaf(p1[j], f.x, a1x); a1y = fmaf(p1[j], f.y, a1y);
                a2x = fmaf(p2[j], f.x, a2x); a2y = fmaf(p2[j], f.y, a2y);
            }
        }
    }
    float pp = post0[gw];
    *(__half2*)(out0 + (size_t)gw * F + lane * 2) = __floats2half2_rn(pp * a0x, pp * a0y);
    *(__half2*)(out1 + (size_t)gw * 128 + lane * 2) = __floats2half2_rn(a1x, a1y);
    *(__half2*)(out2 + (size_t)gw * 128 + 64 + lane * 2) = __floats2half2_rn(a2x, a2y);
}

// ---------------- round-2 fused SpMM: MLP-4 batched 256B gathers -------------
__global__ void k_spmm2(int n) {
    int dir = blockIdx.y;
    int gw = (blockIdx.x * blockDim.x + threadIdx.x) >> 5;
    int lane = threadIdx.x & 31;
    if (gw >= n) return;
    const int* off = dir ? g_col_off : g_row_off;
    const int* nbr = dir ? g_csc_row : g_csr_col;
    const uint2* in = (const uint2*)(dir ? g_vz : g_uw);

    int s = off[gw], e = off[gw + 1];
    float a0 = 0.f, a1 = 0.f, a2 = 0.f, a3 = 0.f;
    for (int base = s; base < e; base += 32) {
        int idx = base + lane;
        int myn = 0;
        float wt = 0.f;
        if (idx < e) { myn = __ldg(nbr + idx); wt = 1.f; }
        int cnt = min(32, e - base);
        for (int k = 0; k < cnt; k += 4) {
            int nd[4]; float wj[4]; uint2 raw[4];
#pragma unroll
            for (int j = 0; j < 4; j++) {
                int kk = k + j;
                nd[j] = __shfl_sync(0xffffffffu, myn, kk);
                wj[j] = __shfl_sync(0xffffffffu, wt, kk);
            }
#pragma unroll
            for (int j = 0; j < 4; j++)
                raw[j] = __ldg(in + (size_t)nd[j] * 32 + lane);
#pragma unroll
            for (int j = 0; j < 4; j++) {
                float2 f0 = __half22float2(*reinterpret_cast<__half2*>(&raw[j].x));
                float2 f1 = __half22float2(*reinterpret_cast<__half2*>(&raw[j].y));
                a0 = fmaf(wj[j], f0.x, a0); a1 = fmaf(wj[j], f0.y, a1);
                a2 = fmaf(wj[j], f1.x, a2); a3 = fmaf(wj[j], f1.y, a3);
            }
        }
    }
    bool partA = lane < 16;
    const float* post = dir ? (partA ? g_post[3] : g_post[5])
                            : (partA ? g_post[2] : g_post[4]);
    __half* outH = dir ? (partA ? g_Hh[3] : g_Hh[5])
                       : (partA ? g_Hh[2] : g_Hh[4]);
    float p = post[gw];
    int fbase = (lane & 15) * 4;
    __half2 o0 = __floats2half2_rn(p * a0, p * a1);
    __half2 o1 = __floats2half2_rn(p * a2, p * a3);
    uint2 st;
    st.x = *reinterpret_cast<uint32_t*>(&o0);
    st.y = *reinterpret_cast<uint32_t*>(&o1);
    *(uint2*)(outH + (size_t)gw * F + fbase) = st;
}

// ---------------- fp16 HMMA GEMM: out = 0.75*(sum H_m W_m + sum b_m) ---------
// H fp16 exact (A operand). W split Whi+Wlo fp16 (B operand), 2 MMAs per tile.
// mma.sync.m16n8k16.row.col.f32.f16.f16.f32
__device__ __forceinline__ void mma_f16(float* c, uint32_t a0, uint32_t a1,
                                        uint32_t a2, uint32_t a3,
                                        uint32_t b0, uint32_t b1) {
    asm volatile(
        "mma.sync.aligned.m16n8k16.row.col.f32.f16.f16.f32 "
        "{%0,%1,%2,%3}, {%4,%5,%6,%7}, {%8,%9}, {%0,%1,%2,%3};"
        : "+f"(c[0]), "+f"(c[1]), "+f"(c[2]), "+f"(c[3])
        : "r"(a0), "r"(a1), "r"(a2), "r"(a3), "r"(b0), "r"(b1));
}

#define LDH 72   // padded half stride: bank = (4g+t) pattern stays conflict-free

__global__ __launch_bounds__(256, 2) void k_gemm(
        const float* __restrict__ W0, const float* __restrict__ W1,
        const float* __restrict__ W2, const float* __restrict__ W3,
        const float* __restrict__ W4, const float* __restrict__ W5,
        const float* __restrict__ B0, const float* __restrict__ B1,
        const float* __restrict__ B2, const float* __restrict__ B3,
        const float* __restrict__ B4, const float* __restrict__ B5,
        float* __restrict__ out, int n) {
    __shared__ __half sH[64 * LDH];     // H tile [row][k]
    __shared__ __half sWhi[64 * LDH];   // W hi, TRANSPOSED [n][k]
    __shared__ __half sWlo[64 * LDH];   // W lo residual,   [n][k]
    __shared__ float sBias[64];
    const float* Ws[6] = {W0, W1, W2, W3, W4, W5};
    const float* Bs[6] = {B0, B1, B2, B3, B4, B5};

    int tid = threadIdx.x;
    int rowBase = blockIdx.x * 64;
    int w = tid >> 5;
    int lane = tid & 31;
    int g = lane >> 2;
    int t = lane & 3;
    int wr = (w & 1) * 32;
    int wc = (w >> 1) * 16;

    if (tid < 64) {
        float s = 0.f;
#pragma unroll
        for (int m = 0; m < 6; m++) s += __ldg(Bs[m] + tid);
        sBias[tid] = s;
    }

    float acc[2][2][4];
#pragma unroll
    for (int i = 0; i < 2; i++)
#pragma unroll
        for (int j = 0; j < 2; j++)
#pragma unroll
            for (int q = 0; q < 4; q++) acc[i][j][q] = 0.f;

#pragma unroll
    for (int m = 0; m < 6; m++) {
        const __half* Hm = g_Hh[m];
        const float* Wm = Ws[m];
        // H tile: 64 rows x 64 halves = 1024 uint2 (4 halves each)
#pragma unroll
        for (int it = 0; it < 4; it++) {
            int idx = tid + it * 256;
            int r = idx >> 4;
            int c4 = (idx & 15) << 2;          // half index, multiple of 4
            int gr = rowBase + r;
            uint2 raw = make_uint2(0u, 0u);
            if (gr < n) raw = __ldg((const uint2*)(Hm) + (size_t)gr * 16 + (idx & 15));
            *(uint2*)(&sH[r * LDH + c4]) = raw;
        }
        // W: 4096 fp32 -> hi/lo fp16, transposed [n][k]
#pragma unroll
        for (int it = 0; it < 16; it++) {
            int idx = tid + it * 256;
            int k = idx >> 6;
            int nn = idx & 63;
            float wv = __ldg(Wm + idx);
            __half hi = __float2half_rn(wv);
            __half lo = __float2half_rn(wv - __half2float(hi));
            sWhi[nn * LDH + k] = hi;
            sWlo[nn * LDH + k] = lo;
        }
        __syncthreads();

#pragma unroll
        for (int kk = 0; kk < 64; kk += 16) {
            uint32_t a[2][4];
#pragma unroll
            for (int mt = 0; mt < 2; mt++) {
                int rbase = wr + mt * 16;
                a[mt][0] = *(const uint32_t*)(&sH[(rbase + g) * LDH + kk + 2 * t]);
                a[mt][1] = *(const uint32_t*)(&sH[(rbase + g + 8) * LDH + kk + 2 * t]);
                a[mt][2] = *(const uint32_t*)(&sH[(rbase + g) * LDH + kk + 2 * t + 8]);
                a[mt][3] = *(const uint32_t*)(&sH[(rbase + g + 8) * LDH + kk + 2 * t + 8]);
            }
            uint32_t bh[2][2], bl[2][2];
#pragma unroll
            for (int nt = 0; nt < 2; nt++) {
                int nbase = wc + nt * 8;
                bh[nt][0] = *(const uint32_t*)(&sWhi[(nbase + g) * LDH + kk + 2 * t]);
                bh[nt][1] = *(const uint32_t*)(&sWhi[(nbase + g) * LDH + kk + 2 * t + 8]);
                bl[nt][0] = *(const uint32_t*)(&sWlo[(nbase + g) * LDH + kk + 2 * t]);
                bl[nt][1] = *(const uint32_t*)(&sWlo[(nbase + g) * LDH + kk + 2 * t + 8]);
            }
#pragma unroll
            for (int mt = 0; mt < 2; mt++)
#pragma unroll
                for (int nt = 0; nt < 2; nt++) {
                    mma_f16(acc[mt][nt], a[mt][0], a[mt][1], a[mt][2], a[mt][3],
                            bl[nt][0], bl[nt][1]);
                    mma_f16(acc[mt][nt], a[mt][0], a[mt][1], a[mt][2], a[mt][3],
                            bh[nt][0], bh[nt][1]);
                }
        }
        __syncthreads();
    }

#pragma unroll
    for (int mt = 0; mt < 2; mt++) {
#pragma unroll
        for (int nt = 0; nt < 2; nt++) {
            int col = wc + nt * 8 + 2 * t;
            float bx = sBias[col], by = sBias[col + 1];
            int r1 = rowBase + wr + mt * 16 + g;
            int r2 = r1 + 8;
            if (r1 < n) {
                float2 o;
                o.x = 0.75f * (acc[mt][nt][0] + bx);
                o.y = 0.75f * (acc[mt][nt][1] + by);
                *(float2*)(out + (size_t)r1 * 64 + col) = o;
            }
            if (r2 < n) {
                float2 o;
                o.x = 0.75f * (acc[mt][nt][2] + bx);
                o.y = 0.75f * (acc[mt][nt][3] + by);
                *(float2*)(out + (size_t)r2 * 64 + col) = o;
            }
        }
    }
}

// ---------------- launcher ----------------
extern "C" void kernel_launch(void* const* d_in, const int* in_sizes, int n_in,
                              void* d_out, int out_size) {
    const float* x = (const float*)d_in[0];
    const int* ei = (const int*)d_in[1];
    const float* W0 = (const float*)d_in[2],  *B0 = (const float*)d_in[3];
    const float* W1 = (const float*)d_in[4],  *B1 = (const float*)d_in[5];
    const float* W2 = (const float*)d_in[6],  *B2 = (const float*)d_in[7];
    const float* W3 = (const float*)d_in[8],  *B3 = (const float*)d_in[9];
    const float* W4 = (const float*)d_in[10], *B4 = (const float*)d_in[11];
    const float* W5 = (const float*)d_in[12], *B5 = (const float*)d_in[13];
    float* out = (float*)d_out;

    int n = in_sizes[0] / F;
    int E = in_sizes[1] / 2;
    if (n > NN) n = NN;
    if (E > EE) E = EE;

    int nb = (n + 255) / 256;
    int eb = (E + 255) / 256;
    int pb = (n + SCAN_B - 1) / SCAN_B;
    int xw = n * 32;                       // half2 words in x

    k_xhalf<<<(xw + 255) / 256, 256>>>(x, xw, n);
    k_hist<<<eb, 256>>>(ei, E);
    k_scan_part<<<dim3(pb, 2), 256>>>(n);
    k_scan_mid<<<1, 128>>>(pb);
    k_scan_final<<<dim3(pb, 2), SCAN_B>>>(n, pb);
    k_scatter<<<eb, 256>>>(ei, E);
    k_degspmv<<<dim3(nb, 2), 256>>>(n);
    k_scales<<<nb, 256>>>(n);

    int sb = (n + 7) / 8;   // warp-per-node, 8 warps/block
    k_spmm3<<<dim3(sb, 2), 256>>>(n);
    k_spmm2<<<dim3(sb, 2), 256>>>(n);

    int gb = (n + 63) / 64;
    k_gemm<<<gb, 256>>>(W0, W1, W2, W3, W4, W5,
                        B0, B1, B2, B3, B4, B5, out, n);
}